// round 1
// baseline (speedup 1.0000x reference)
#include <cuda_runtime.h>
#include <cuda_bf16.h>
#include <math.h>

#define W 512
#define NPIX (512*512)
#define ZM 30
#define NF 16
#define TOT (ZM*NPIX)

// ---------------- scratch (device globals, no allocation) ----------------
__device__ float2 g_buf0[TOT];
__device__ float2 g_buf1[TOT];
__device__ float2 g_buf2[TOT];
__device__ float  g_fluo[TOT];
__device__ float  g_zfeat[ZM*NF];
__device__ float  g_invS;          // 262144 / sum(pupil)
__device__ float2 g_tw[256];       // forward twiddles exp(-2*pi*i*k/512)

__device__ __forceinline__ float2* pick_buf(int k) {
    return k == 0 ? g_buf0 : (k == 1 ? g_buf1 : g_buf2);
}

// ---------------- prep: twiddles, z-feature interp, pupil sum ----------------
__global__ void prep_kernel(const float* __restrict__ z,
                            const float* __restrict__ z_data,
                            const float* __restrict__ pupil) {
    int tid = threadIdx.x;
    if (tid < 256) {
        float s_, c_;
        sincospif(-(float)tid * (1.0f / 256.0f), &s_, &c_);  // -2*pi*k/512
        g_tw[tid] = make_float2(c_, s_);
    }
    if (tid < ZM) {
        float zn = 29.0f * z[tid] / 30.0f;
        float zf = floorf(zn);
        int z0 = (int)zf;
        if (z0 < 0) z0 = 0; if (z0 > ZM - 1) z0 = ZM - 1;
        int z1 = z0 + 1; if (z1 > ZM - 1) z1 = ZM - 1;
        float zl = zn - zf;
        for (int f = 0; f < NF; f++)
            g_zfeat[tid * NF + f] = z_data[z0 * NF + f] * (1.0f - zl) + z_data[z1 * NF + f] * zl;
    }
    // pupil sum (exact: 0/1 values, integer < 2^24)
    float acc = 0.0f;
    for (int i = tid; i < NPIX; i += 256) acc += pupil[i];
    __shared__ float red[256];
    red[tid] = acc;
    __syncthreads();
    for (int s = 128; s > 0; s >>= 1) {
        if (tid < s) red[tid] += red[tid + s];
        __syncthreads();
    }
    if (tid == 0) g_invS = 262144.0f / red[0];
}

// ---------------- render: bilinear grid feature * z feature -> MLP ----------------
__global__ __launch_bounds__(128)
void render_kernel(const float* __restrict__ grid_data,
                   const float* __restrict__ w1, const float* __restrict__ b1,
                   const float* __restrict__ w2, const float* __restrict__ b2,
                   const float* __restrict__ w3, const float* __restrict__ b3,
                   const float* __restrict__ lerp_w,
                   const int* __restrict__ x0, const int* __restrict__ y0,
                   const int* __restrict__ x1, const int* __restrict__ y1) {
    __shared__ float sw1[NF * 32], sw2[32 * 32], sb1[32], sb2[32], sw3[32], szf[ZM * NF];
    __shared__ float sb3;
    int tid = threadIdx.x;
    for (int i = tid; i < NF * 32; i += 128) sw1[i] = w1[i];
    for (int i = tid; i < 32 * 32; i += 128) sw2[i] = w2[i];
    for (int i = tid; i < ZM * NF; i += 128) szf[i] = g_zfeat[i];
    if (tid < 32) { sb1[tid] = b1[tid]; sb2[tid] = b2[tid]; sw3[tid] = w3[tid]; }
    if (tid == 0) sb3 = b3[0];
    __syncthreads();

    int p = blockIdx.x * 128 + tid;
    if (p >= NPIX) return;

    float lx = lerp_w[2 * p], ly = lerp_w[2 * p + 1];
    int X0 = x0[p], Y0 = y0[p], X1 = x1[p], Y1 = y1[p];
    const float* g00 = grid_data + (Y0 * W + X0) * NF;
    const float* g01 = grid_data + (Y0 * W + X1) * NF;
    const float* g10 = grid_data + (Y1 * W + X0) * NF;
    const float* g11 = grid_data + (Y1 * W + X1) * NF;
    float c00 = (1.0f - lx) * (1.0f - ly);
    float c01 = lx * (1.0f - ly);
    float c10 = (1.0f - lx) * ly;
    float c11 = lx * ly;

    float xy[NF];
#pragma unroll
    for (int f = 0; f < NF; f++)
        xy[f] = g00[f] * c00 + g01[f] * c01 + g10[f] * c10 + g11[f] * c11;

    for (int zz = 0; zz < ZM; zz++) {
        float h1[32];
#pragma unroll
        for (int j = 0; j < 32; j++) h1[j] = sb1[j];
#pragma unroll
        for (int f = 0; f < NF; f++) {
            float ff = xy[f] * szf[zz * NF + f];
#pragma unroll
            for (int j = 0; j < 32; j++) h1[j] = fmaf(ff, sw1[f * 32 + j], h1[j]);
        }
#pragma unroll
        for (int j = 0; j < 32; j++) h1[j] = fmaxf(h1[j], 0.0f);
        float h2[32];
#pragma unroll
        for (int j = 0; j < 32; j++) h2[j] = sb2[j];
#pragma unroll
        for (int k = 0; k < 32; k++) {
            float hk = h1[k];
#pragma unroll
            for (int j = 0; j < 32; j++) h2[j] = fmaf(hk, sw2[k * 32 + j], h2[j]);
        }
        float o = sb3;
#pragma unroll
        for (int j = 0; j < 32; j++) o = fmaf(fmaxf(h2[j], 0.0f), sw3[j], o);
        g_fluo[zz * NPIX + p] = o;
    }
}

// ---------------- build pupil function P = pupil * exp(i*ab) ----------------
__global__ void buildP_kernel(const float* __restrict__ pupil,
                              const float* __restrict__ ab) {
    int i = blockIdx.x * 256 + threadIdx.x;
    if (i >= TOT) return;
    int pix = i & (NPIX - 1);
    float pv = pupil[pix];
    float sn, cs;
    sincosf(ab[i], &sn, &cs);
    g_buf0[i] = make_float2(pv * cs, pv * sn);
}

// ---------------- batched 512-pt radix-2 FFT ----------------
// DIR: -1 forward, +1 inverse. LM: 0 complex-from-buf, 1 real-from-g_fluo.
// SM: 0 complex-to-buf, 1 |v|^2 (imag=0) to buf, 2 real part to rout.
template <int DIR, int LM, int SM>
__global__ __launch_bounds__(128)
void fft512_kernel(int inb, int outb, float* __restrict__ rout,
                   int stride, int dist, float scale) {
    __shared__ float2 s[512];
    const float2* in = (LM == 0) ? pick_buf(inb) : nullptr;
    float2* out = (SM != 2) ? pick_buf(outb) : nullptr;
    int t = blockIdx.x, sl = blockIdx.y;
    int base = sl * NPIX + t * dist;
    int tid = threadIdx.x;

    for (int i = tid; i < 512; i += 128) {
        float2 v;
        if (LM == 0) v = in[base + i * stride];
        else         v = make_float2(g_fluo[base + i * stride], 0.0f);
        s[__brev((unsigned)i) >> 23] = v;   // bit-reversed placement
    }

#pragma unroll
    for (int st = 1; st <= 9; st++) {
        int half = 1 << (st - 1);
        __syncthreads();
#pragma unroll
        for (int r = 0; r < 2; r++) {
            int b = tid + r * 128;                // 256 butterflies / stage
            int j = b & (half - 1);
            int g = b >> (st - 1);
            int i0 = (g << st) + j;
            int i1 = i0 + half;
            float2 w = g_tw[j << (9 - st)];
            if (DIR > 0) w.y = -w.y;              // conj for inverse
            float2 a = s[i0], c = s[i1];
            float2 tt = make_float2(c.x * w.x - c.y * w.y,
                                    c.x * w.y + c.y * w.x);
            s[i0] = make_float2(a.x + tt.x, a.y + tt.y);
            s[i1] = make_float2(a.x - tt.x, a.y - tt.y);
        }
    }
    __syncthreads();

    for (int i = tid; i < 512; i += 128) {
        float2 v = s[i];
        v.x *= scale; v.y *= scale;
        int o = base + i * stride;
        if (SM == 0)      out[o] = v;
        else if (SM == 1) out[o] = make_float2(v.x * v.x + v.y * v.y, 0.0f);
        else              rout[o] = v.x;
    }
}

// ---------------- pointwise: F *= OTF * invS ----------------
__global__ void cmul_kernel() {
    int i = blockIdx.x * 256 + threadIdx.x;
    if (i >= TOT) return;
    float sc = g_invS;
    float2 x = g_buf2[i], y = g_buf0[i];
    g_buf2[i] = make_float2((x.x * y.x - x.y * y.y) * sc,
                            (x.x * y.y + x.y * y.x) * sc);
}

// ---------------- launch ----------------
extern "C" void kernel_launch(void* const* d_in, const int* in_sizes, int n_in,
                              void* d_out, int out_size) {
    const float* z         = (const float*)d_in[0];
    const float* grid_data = (const float*)d_in[1];
    const float* z_data    = (const float*)d_in[2];
    const float* w1        = (const float*)d_in[3];
    const float* b1        = (const float*)d_in[4];
    const float* w2        = (const float*)d_in[5];
    const float* b2        = (const float*)d_in[6];
    const float* w3        = (const float*)d_in[7];
    const float* b3        = (const float*)d_in[8];
    const float* pupil     = (const float*)d_in[9];
    const float* ab        = (const float*)d_in[10];
    const float* lerp_w    = (const float*)d_in[11];
    const int*   x0        = (const int*)d_in[12];
    const int*   y0        = (const int*)d_in[13];
    const int*   x1        = (const int*)d_in[14];
    const int*   y1        = (const int*)d_in[15];
    float* outp = (float*)d_out;

    prep_kernel<<<1, 256>>>(z, z_data, pupil);
    render_kernel<<<NPIX / 128, 128>>>(grid_data, w1, b1, w2, b2, w3, b3,
                                       lerp_w, x0, y0, x1, y1);
    buildP_kernel<<<(TOT + 255) / 256, 256>>>(pupil, ab);

    dim3 g(512, ZM);
    const float inv = 1.0f / 512.0f;
    // ifft2(P): rows then cols, fused |.|^2 on the final store  -> psf (buf0)
    fft512_kernel<+1, 0, 0><<<g, 128>>>(0, 1, nullptr, 1, 512, inv);
    fft512_kernel<+1, 0, 1><<<g, 128>>>(1, 0, nullptr, 512, 1, inv);
    // fft2(psf) -> OTF (unnormalized, buf0)
    fft512_kernel<-1, 0, 0><<<g, 128>>>(0, 1, nullptr, 1, 512, 1.0f);
    fft512_kernel<-1, 0, 0><<<g, 128>>>(1, 0, nullptr, 512, 1, 1.0f);
    // fft2(fluo) -> F (buf2)
    fft512_kernel<-1, 1, 0><<<g, 128>>>(0, 1, nullptr, 1, 512, 1.0f);
    fft512_kernel<-1, 0, 0><<<g, 128>>>(1, 2, nullptr, 512, 1, 1.0f);
    // F *= OTF * (N^2 / sum(pupil))
    cmul_kernel<<<(TOT + 255) / 256, 256>>>();
    // ifft2 -> real output
    fft512_kernel<+1, 0, 0><<<g, 128>>>(2, 1, nullptr, 1, 512, inv);
    fft512_kernel<+1, 0, 2><<<g, 128>>>(1, 0, outp, 512, 1, inv);
}

// round 6
// speedup vs baseline: 1.0448x; 1.0448x over previous
#include <cuda_runtime.h>
#include <cuda_bf16.h>
#include <math.h>

#define W 512
#define NPIX (512*512)
#define ZM 30
#define NF 16
#define TOT (ZM*NPIX)
#define SROW 580   // padded shared row (512 + 512/8 = 576 max index 574)

// ---------------- scratch (device globals, no allocation) ----------------
__device__ float2 g_buf0[TOT];
__device__ float2 g_buf1[TOT];
__device__ float2 g_buf2[TOT];
__device__ float  g_fluo[TOT];
__device__ float  g_psf[TOT];
__device__ float  g_zfeat[ZM*NF];
__device__ float  g_invS;          // 262144 / sum(pupil)
__device__ float2 g_twid[512];     // forward twiddles exp(-2*pi*i*k/512)

__device__ __forceinline__ float2* pick_buf(int k) {
    return k == 0 ? g_buf0 : (k == 1 ? g_buf1 : g_buf2);
}
__device__ __forceinline__ float* pick_real(int k, float* ext) {
    return k == 0 ? g_fluo : (k == 1 ? g_psf : ext);
}
__device__ __forceinline__ int PAD(int i) { return i + (i >> 3); }

__device__ __forceinline__ float2 cadd(float2 a, float2 b){ return make_float2(a.x+b.x, a.y+b.y); }
__device__ __forceinline__ float2 csub(float2 a, float2 b){ return make_float2(a.x-b.x, a.y-b.y); }
__device__ __forceinline__ float2 cmulc(float2 a, float2 b){
    return make_float2(a.x*b.x - a.y*b.y, a.x*b.y + a.y*b.x);
}
// multiply by i*DIR
template<int DIR> __device__ __forceinline__ float2 muli(float2 a){
    return (DIR > 0) ? make_float2(-a.y, a.x) : make_float2(a.y, -a.x);
}

// 8-point DFT in registers, b_r = sum_q a_q * exp(DIR*2*pi*i*q*r/8)
template<int DIR>
__device__ __forceinline__ void dft8(float2* a){
    const float S = 0.70710678118654752440f;
    float2 e0 = cadd(a[0], a[4]), e1 = csub(a[0], a[4]);
    float2 e2 = cadd(a[2], a[6]), e3 = csub(a[2], a[6]);
    float2 E0 = cadd(e0, e2), E2 = csub(e0, e2);
    float2 ie3 = muli<DIR>(e3);
    float2 E1 = cadd(e1, ie3), E3 = csub(e1, ie3);

    float2 o0 = cadd(a[1], a[5]), o1 = csub(a[1], a[5]);
    float2 o2 = cadd(a[3], a[7]), o3 = csub(a[3], a[7]);
    float2 O0 = cadd(o0, o2), O2 = csub(o0, o2);
    float2 io3 = muli<DIR>(o3);
    float2 O1 = cadd(o1, io3), O3 = csub(o1, io3);

    // w^1 = (S, DIR*S), w^2 = i*DIR, w^3 = (-S, DIR*S)
    float2 W1, W3;
    if (DIR > 0) {
        W1 = make_float2(S*(O1.x - O1.y), S*(O1.x + O1.y));
        W3 = make_float2(-S*(O3.x + O3.y), S*(O3.x - O3.y));
    } else {
        W1 = make_float2(S*(O1.x + O1.y), S*(O1.y - O1.x));
        W3 = make_float2(S*(O3.y - O3.x), -S*(O3.x + O3.y));
    }
    float2 W2 = muli<DIR>(O2);

    a[0] = cadd(E0, O0); a[4] = csub(E0, O0);
    a[1] = cadd(E1, W1); a[5] = csub(E1, W1);
    a[2] = cadd(E2, W2); a[6] = csub(E2, W2);
    a[3] = cadd(E3, W3); a[7] = csub(E3, W3);
}

// ---------------- prep: twiddles, z-feature interp, pupil sum ----------------
__global__ void prep_kernel(const float* __restrict__ z,
                            const float* __restrict__ z_data,
                            const float* __restrict__ pupil) {
    int tid = threadIdx.x;   // 512 threads
    {
        float s_, c_;
        sincospif(-(float)tid * (1.0f / 256.0f), &s_, &c_);  // -2*pi*tid/512
        g_twid[tid] = make_float2(c_, s_);
    }
    if (tid < ZM) {
        float zn = 29.0f * z[tid] / 30.0f;
        float zf = floorf(zn);
        int z0 = (int)zf;
        if (z0 < 0) z0 = 0; if (z0 > ZM - 1) z0 = ZM - 1;
        int z1 = z0 + 1; if (z1 > ZM - 1) z1 = ZM - 1;
        float zl = zn - zf;
        for (int f = 0; f < NF; f++)
            g_zfeat[tid * NF + f] = z_data[z0 * NF + f] * (1.0f - zl) + z_data[z1 * NF + f] * zl;
    }
    float acc = 0.0f;
    for (int i = tid; i < NPIX; i += 512) acc += pupil[i];
    __shared__ float red[512];
    red[tid] = acc;
    __syncthreads();
    for (int s = 256; s > 0; s >>= 1) {
        if (tid < s) red[tid] += red[tid + s];
        __syncthreads();
    }
    if (tid == 0) g_invS = 262144.0f / red[0];
}

// ---------------- render: bilinear feature * z feature -> MLP (float4 weights) ----------------
__global__ __launch_bounds__(128)
void render_kernel(const float* __restrict__ grid_data,
                   const float* __restrict__ w1, const float* __restrict__ b1,
                   const float* __restrict__ w2, const float* __restrict__ b2,
                   const float* __restrict__ w3, const float* __restrict__ b3,
                   const float* __restrict__ lerp_w,
                   const int* __restrict__ x0, const int* __restrict__ y0,
                   const int* __restrict__ x1, const int* __restrict__ y1) {
    __shared__ float4 sw1v[NF * 8];     // w1[16][32]
    __shared__ float4 sw2v[32 * 8];     // w2[32][32]
    __shared__ float4 sw3v[8];          // w3[32]
    __shared__ float  sb1[32], sb2[32], szf[ZM * NF];
    __shared__ float  sb3;
    int tid = threadIdx.x;
    for (int i = tid; i < NF * 8; i += 128) sw1v[i] = ((const float4*)w1)[i];
    for (int i = tid; i < 32 * 8; i += 128) sw2v[i] = ((const float4*)w2)[i];
    if (tid < 8)  sw3v[tid] = ((const float4*)w3)[tid];
    for (int i = tid; i < ZM * NF; i += 128) szf[i] = g_zfeat[i];
    if (tid < 32) { sb1[tid] = b1[tid]; sb2[tid] = b2[tid]; }
    if (tid == 0) sb3 = b3[0];
    __syncthreads();

    int p = blockIdx.x * 128 + tid;

    float lx = lerp_w[2 * p], ly = lerp_w[2 * p + 1];
    int X0 = x0[p], Y0 = y0[p], X1 = x1[p], Y1 = y1[p];
    const float4* g00 = (const float4*)(grid_data + (Y0 * W + X0) * NF);
    const float4* g01 = (const float4*)(grid_data + (Y0 * W + X1) * NF);
    const float4* g10 = (const float4*)(grid_data + (Y1 * W + X0) * NF);
    const float4* g11 = (const float4*)(grid_data + (Y1 * W + X1) * NF);
    float c00 = (1.0f - lx) * (1.0f - ly);
    float c01 = lx * (1.0f - ly);
    float c10 = (1.0f - lx) * ly;
    float c11 = lx * ly;

    float xy[NF];
#pragma unroll
    for (int q = 0; q < 4; q++) {
        float4 a = g00[q], b = g01[q], c = g10[q], d = g11[q];
        xy[4*q+0] = a.x*c00 + b.x*c01 + c.x*c10 + d.x*c11;
        xy[4*q+1] = a.y*c00 + b.y*c01 + c.y*c10 + d.y*c11;
        xy[4*q+2] = a.z*c00 + b.z*c01 + c.z*c10 + d.z*c11;
        xy[4*q+3] = a.w*c00 + b.w*c01 + c.w*c10 + d.w*c11;
    }

#pragma unroll 1
    for (int zz = 0; zz < ZM; zz++) {
        float h1[32];
#pragma unroll
        for (int j = 0; j < 32; j++) h1[j] = sb1[j];
#pragma unroll
        for (int f = 0; f < NF; f++) {
            float ff = xy[f] * szf[zz * NF + f];
#pragma unroll
            for (int jq = 0; jq < 8; jq++) {
                float4 w = sw1v[f * 8 + jq];
                h1[4*jq+0] = fmaf(ff, w.x, h1[4*jq+0]);
                h1[4*jq+1] = fmaf(ff, w.y, h1[4*jq+1]);
                h1[4*jq+2] = fmaf(ff, w.z, h1[4*jq+2]);
                h1[4*jq+3] = fmaf(ff, w.w, h1[4*jq+3]);
            }
        }
#pragma unroll
        for (int j = 0; j < 32; j++) h1[j] = fmaxf(h1[j], 0.0f);

        float h2[32];
#pragma unroll
        for (int j = 0; j < 32; j++) h2[j] = sb2[j];
#pragma unroll
        for (int k = 0; k < 32; k++) {
            float hk = h1[k];
#pragma unroll
            for (int jq = 0; jq < 8; jq++) {
                float4 w = sw2v[k * 8 + jq];
                h2[4*jq+0] = fmaf(hk, w.x, h2[4*jq+0]);
                h2[4*jq+1] = fmaf(hk, w.y, h2[4*jq+1]);
                h2[4*jq+2] = fmaf(hk, w.z, h2[4*jq+2]);
                h2[4*jq+3] = fmaf(hk, w.w, h2[4*jq+3]);
            }
        }
        float o = sb3;
#pragma unroll
        for (int jq = 0; jq < 8; jq++) {
            float4 w = sw3v[jq];
            o = fmaf(fmaxf(h2[4*jq+0], 0.0f), w.x, o);
            o = fmaf(fmaxf(h2[4*jq+1], 0.0f), w.y, o);
            o = fmaf(fmaxf(h2[4*jq+2], 0.0f), w.z, o);
            o = fmaf(fmaxf(h2[4*jq+3], 0.0f), w.w, o);
        }
        g_fluo[zz * NPIX + p] = o;
    }
}

// ---------------- batched 512-pt Stockham radix-8 FFT ----------------
// DIR: -1 forward, +1 inverse.
// LM: 0 complex from pick_buf(inb); 1 real from pick_real(rinsel); 2 pupil*exp(i*ab); 3 buf(inb)*buf(in2b)*invS
// SM: 0 complex to pick_buf(outb); 1 |v|^2 to pick_real(routsel); 2 v.x to pick_real(routsel)
// COL: 0 row pass (contiguous), 1 column pass (stride 512, cooperative I/O)
template <int DIR, int LM, int SM, int COL>
__global__ __launch_bounds__(256)
void fft512_kernel(int inb, int in2b, int outb, int rinsel, int routsel,
                   float* ext, const float* __restrict__ pupil,
                   const float* __restrict__ ab, float scale) {
    __shared__ float2 sA[4][SROW];
    __shared__ float2 sB[4][SROW];
    __shared__ float2 stw[512];

    int tid = threadIdx.x;
    int sub = tid >> 6, t = tid & 63;
    int sl = blockIdx.y, g4 = blockIdx.x * 4;

    for (int i = tid; i < 512; i += 256) stw[i] = g_twid[i];

    const float2* in  = pick_buf(inb);
    const float2* in2 = pick_buf(in2b);
    const float*  rin = pick_real(rinsel, nullptr);

    // ---- load ----
    if (COL == 0) {
        int row = g4 + sub;
        long base = (long)sl * NPIX + (long)row * 512;
        float sc = (LM == 3) ? g_invS : 0.0f;
#pragma unroll
        for (int r = 0; r < 8; r++) {
            int i = t + 64 * r;
            float2 v;
            if (LM == 0) v = in[base + i];
            else if (LM == 1) v = make_float2(rin[base + i], 0.0f);
            else if (LM == 2) {
                float pv = pupil[row * 512 + i];
                float sn, cs;
                sincosf(ab[base + i], &sn, &cs);
                v = make_float2(pv * cs, pv * sn);
            } else {
                float2 x = in[base + i], y = in2[base + i];
                v = make_float2((x.x*y.x - x.y*y.y) * sc, (x.x*y.y + x.y*y.x) * sc);
            }
            sA[sub][PAD(i)] = v;
        }
    } else {
        long base = (long)sl * NPIX + g4;
#pragma unroll
        for (int it = 0; it < 8; it++) {
            int row = it * 64 + (tid >> 2);
            int c = tid & 3;
            long adr = base + (long)row * 512 + c;
            float2 v;
            if (LM == 1) v = make_float2(rin[adr], 0.0f);
            else         v = in[adr];
            sA[c][PAD(row)] = v;
        }
    }
    __syncthreads();

    // ---- stage 1: ns=1 (sA -> sB) ----
    {
        float2 a[8];
#pragma unroll
        for (int r = 0; r < 8; r++) a[r] = sA[sub][PAD(t + 64 * r)];
        dft8<DIR>(a);
#pragma unroll
        for (int r = 0; r < 8; r++) sB[sub][PAD(t * 8 + r)] = a[r];
    }
    __syncthreads();

    // ---- stage 2: ns=8 (sB -> sA) ----
    {
        float2 a[8];
#pragma unroll
        for (int r = 0; r < 8; r++) a[r] = sB[sub][PAD(t + 64 * r)];
        int k = t & 7;
#pragma unroll
        for (int r = 1; r < 8; r++) {
            float2 w = stw[(k * r * 8) & 511];
            if (DIR > 0) w.y = -w.y;
            a[r] = cmulc(a[r], w);
        }
        dft8<DIR>(a);
        int bidx = (t >> 3) * 64 + k;
#pragma unroll
        for (int r = 0; r < 8; r++) sA[sub][PAD(bidx + 8 * r)] = a[r];
    }
    __syncthreads();

    // ---- stage 3: ns=64 (sA -> sB), apply scale ----
    {
        float2 a[8];
#pragma unroll
        for (int r = 0; r < 8; r++) a[r] = sA[sub][PAD(t + 64 * r)];
#pragma unroll
        for (int r = 1; r < 8; r++) {
            float2 w = stw[t * r];
            if (DIR > 0) w.y = -w.y;
            a[r] = cmulc(a[r], w);
        }
        dft8<DIR>(a);
#pragma unroll
        for (int r = 0; r < 8; r++)
            sB[sub][PAD(t + 64 * r)] = make_float2(a[r].x * scale, a[r].y * scale);
    }
    __syncthreads();

    // ---- store ----
    float2* outc = pick_buf(outb);
    float*  routp = pick_real(routsel, ext);
    if (COL == 0) {
        int row = g4 + sub;
        long base = (long)sl * NPIX + (long)row * 512;
#pragma unroll
        for (int r = 0; r < 8; r++) {
            int i = t + 64 * r;
            float2 v = sB[sub][PAD(i)];
            if (SM == 0)      outc[base + i] = v;
            else if (SM == 1) routp[base + i] = v.x*v.x + v.y*v.y;
            else              routp[base + i] = v.x;
        }
    } else {
        long base = (long)sl * NPIX + g4;
#pragma unroll
        for (int it = 0; it < 8; it++) {
            int row = it * 64 + (tid >> 2);
            int c = tid & 3;
            long adr = base + (long)row * 512 + c;
            float2 v = sB[c][PAD(row)];
            if (SM == 0)      outc[adr] = v;
            else if (SM == 1) routp[adr] = v.x*v.x + v.y*v.y;
            else              routp[adr] = v.x;
        }
    }
}

// ---------------- launch ----------------
extern "C" void kernel_launch(void* const* d_in, const int* in_sizes, int n_in,
                              void* d_out, int out_size) {
    const float* z         = (const float*)d_in[0];
    const float* grid_data = (const float*)d_in[1];
    const float* z_data    = (const float*)d_in[2];
    const float* w1        = (const float*)d_in[3];
    const float* b1        = (const float*)d_in[4];
    const float* w2        = (const float*)d_in[5];
    const float* b2        = (const float*)d_in[6];
    const float* w3        = (const float*)d_in[7];
    const float* b3        = (const float*)d_in[8];
    const float* pupil     = (const float*)d_in[9];
    const float* ab        = (const float*)d_in[10];
    const float* lerp_w    = (const float*)d_in[11];
    const int*   x0        = (const int*)d_in[12];
    const int*   y0        = (const int*)d_in[13];
    const int*   x1        = (const int*)d_in[14];
    const int*   y1        = (const int*)d_in[15];
    float* outp = (float*)d_out;

    prep_kernel<<<1, 512>>>(z, z_data, pupil);
    render_kernel<<<NPIX / 128, 128>>>(grid_data, w1, b1, w2, b2, w3, b3,
                                       lerp_w, x0, y0, x1, y1);

    dim3 g(128, ZM);
    const float inv = 1.0f / 512.0f;
    // ifft2(P) with fused pupil*exp(i*ab) build; |.|^2 -> psf (real)
    fft512_kernel<+1, 2, 0, 0><<<g, 256>>>(0, 0, 1, 0, 0, nullptr, pupil, ab, inv);
    fft512_kernel<+1, 0, 1, 1><<<g, 256>>>(1, 0, 0, 0, 1, nullptr, nullptr, nullptr, inv);
    // fft2(psf) -> OTF (buf0)
    fft512_kernel<-1, 1, 0, 0><<<g, 256>>>(0, 0, 1, 1, 0, nullptr, nullptr, nullptr, 1.0f);
    fft512_kernel<-1, 0, 0, 1><<<g, 256>>>(1, 0, 0, 0, 0, nullptr, nullptr, nullptr, 1.0f);
    // fft2(fluo) -> F (buf2)
    fft512_kernel<-1, 1, 0, 0><<<g, 256>>>(0, 0, 1, 0, 0, nullptr, nullptr, nullptr, 1.0f);
    fft512_kernel<-1, 0, 0, 1><<<g, 256>>>(1, 0, 2, 0, 0, nullptr, nullptr, nullptr, 1.0f);
    // ifft2(F * OTF * invS) -> real out  (cmul fused into row-pass load)
    fft512_kernel<+1, 3, 0, 0><<<g, 256>>>(2, 0, 1, 0, 0, nullptr, nullptr, nullptr, inv);
    fft512_kernel<+1, 0, 2, 1><<<g, 256>>>(1, 0, 0, 0, 2, outp, nullptr, nullptr, inv);
}

// round 7
// speedup vs baseline: 8.9063x; 8.5247x over previous
#include <cuda_runtime.h>
#include <cuda_bf16.h>
#include <math.h>

#define W 512
#define NPIX (512*512)
#define ZM 30
#define NF 16
#define TOT (ZM*NPIX)
#define SROW 580   // padded shared row (512 + 512/8 = 576 max index 574)

// ---------------- scratch (device globals, no allocation) ----------------
__device__ float2 g_buf0[TOT];
__device__ float2 g_buf1[TOT];
__device__ float2 g_buf2[TOT];
__device__ float  g_fluo[TOT];
__device__ float  g_psf[TOT];
__device__ float  g_zfeat[ZM*NF];
__device__ float  g_invS;          // 262144 / sum(pupil)
__device__ float2 g_twid[512];     // forward twiddles exp(-2*pi*i*k/512)

__device__ __forceinline__ float2* pick_buf(int k) {
    return k == 0 ? g_buf0 : (k == 1 ? g_buf1 : g_buf2);
}
__device__ __forceinline__ float* pick_real(int k, float* ext) {
    return k == 0 ? g_fluo : (k == 1 ? g_psf : ext);
}
__device__ __forceinline__ int PAD(int i) { return i + (i >> 3); }

__device__ __forceinline__ float2 cadd(float2 a, float2 b){ return make_float2(a.x+b.x, a.y+b.y); }
__device__ __forceinline__ float2 csub(float2 a, float2 b){ return make_float2(a.x-b.x, a.y-b.y); }
__device__ __forceinline__ float2 cmulc(float2 a, float2 b){
    return make_float2(a.x*b.x - a.y*b.y, a.x*b.y + a.y*b.x);
}
// multiply by i*DIR
template<int DIR> __device__ __forceinline__ float2 muli(float2 a){
    return (DIR > 0) ? make_float2(-a.y, a.x) : make_float2(a.y, -a.x);
}

// 8-point DFT in registers, b_r = sum_q a_q * exp(DIR*2*pi*i*q*r/8)
template<int DIR>
__device__ __forceinline__ void dft8(float2* a){
    const float S = 0.70710678118654752440f;
    float2 e0 = cadd(a[0], a[4]), e1 = csub(a[0], a[4]);
    float2 e2 = cadd(a[2], a[6]), e3 = csub(a[2], a[6]);
    float2 E0 = cadd(e0, e2), E2 = csub(e0, e2);
    float2 ie3 = muli<DIR>(e3);
    float2 E1 = cadd(e1, ie3), E3 = csub(e1, ie3);

    float2 o0 = cadd(a[1], a[5]), o1 = csub(a[1], a[5]);
    float2 o2 = cadd(a[3], a[7]), o3 = csub(a[3], a[7]);
    float2 O0 = cadd(o0, o2), O2 = csub(o0, o2);
    float2 io3 = muli<DIR>(o3);
    float2 O1 = cadd(o1, io3), O3 = csub(o1, io3);

    float2 W1, W3;
    if (DIR > 0) {
        W1 = make_float2(S*(O1.x - O1.y), S*(O1.x + O1.y));
        W3 = make_float2(-S*(O3.x + O3.y), S*(O3.x - O3.y));
    } else {
        W1 = make_float2(S*(O1.x + O1.y), S*(O1.y - O1.x));
        W3 = make_float2(S*(O3.y - O3.x), -S*(O3.x + O3.y));
    }
    float2 W2 = muli<DIR>(O2);

    a[0] = cadd(E0, O0); a[4] = csub(E0, O0);
    a[1] = cadd(E1, W1); a[5] = csub(E1, W1);
    a[2] = cadd(E2, W2); a[6] = csub(E2, W2);
    a[3] = cadd(E3, W3); a[7] = csub(E3, W3);
}

// ---------------- prep: twiddles, z-feature interp, pupil sum ----------------
__global__ void prep_kernel(const float* __restrict__ z,
                            const float* __restrict__ z_data,
                            const float* __restrict__ pupil) {
    int tid = threadIdx.x;   // 512 threads
    {
        float s_, c_;
        sincospif(-(float)tid * (1.0f / 256.0f), &s_, &c_);  // -2*pi*tid/512
        g_twid[tid] = make_float2(c_, s_);
    }
    if (tid < ZM) {
        float zn = 29.0f * z[tid] / 30.0f;
        float zf = floorf(zn);
        int z0 = (int)zf;
        if (z0 < 0) z0 = 0; if (z0 > ZM - 1) z0 = ZM - 1;
        int z1 = z0 + 1; if (z1 > ZM - 1) z1 = ZM - 1;
        float zl = zn - zf;
        for (int f = 0; f < NF; f++)
            g_zfeat[tid * NF + f] = z_data[z0 * NF + f] * (1.0f - zl) + z_data[z1 * NF + f] * zl;
    }
    float acc = 0.0f;
    for (int i = tid; i < NPIX; i += 512) acc += pupil[i];
    __shared__ float red[512];
    red[tid] = acc;
    __syncthreads();
    for (int s = 256; s > 0; s >>= 1) {
        if (tid < s) red[tid] += red[tid + s];
        __syncthreads();
    }
    if (tid == 0) g_invS = 262144.0f / red[0];
}

// ---------------- render: one (pixel, z) per thread; z = blockIdx.y ----------------
__global__ __launch_bounds__(256)
void render_kernel(const float* __restrict__ grid_data,
                   const float* __restrict__ w1, const float* __restrict__ b1,
                   const float* __restrict__ w2, const float* __restrict__ b2,
                   const float* __restrict__ w3, const float* __restrict__ b3,
                   const float* __restrict__ lerp_w,
                   const int* __restrict__ x0, const int* __restrict__ y0,
                   const int* __restrict__ x1, const int* __restrict__ y1) {
    __shared__ float4 sw1v[NF * 8];     // w1[16][32]
    __shared__ float4 sw2v[32 * 8];     // w2[32][32]
    __shared__ float4 sw3v[8];          // w3[32]
    __shared__ float  sb1[32], sb2[32], szf[NF];
    __shared__ float  sb3;
    int tid = threadIdx.x;
    int zz = blockIdx.y;
    if (tid < NF * 8)  sw1v[tid] = ((const float4*)w1)[tid];
    sw2v[tid] = ((const float4*)w2)[tid];
    if (tid < 8)  sw3v[tid] = ((const float4*)w3)[tid];
    if (tid < NF) szf[tid] = g_zfeat[zz * NF + tid];
    if (tid >= 32 && tid < 64)  sb1[tid - 32] = b1[tid - 32];
    if (tid >= 64 && tid < 96)  sb2[tid - 64] = b2[tid - 64];
    if (tid == 96) sb3 = b3[0];
    __syncthreads();

    int p = blockIdx.x * 256 + tid;

    float lx = lerp_w[2 * p], ly = lerp_w[2 * p + 1];
    int X0 = x0[p], Y0 = y0[p], X1 = x1[p], Y1 = y1[p];
    const float4* g00 = (const float4*)(grid_data + (Y0 * W + X0) * NF);
    const float4* g01 = (const float4*)(grid_data + (Y0 * W + X1) * NF);
    const float4* g10 = (const float4*)(grid_data + (Y1 * W + X0) * NF);
    const float4* g11 = (const float4*)(grid_data + (Y1 * W + X1) * NF);
    float c00 = (1.0f - lx) * (1.0f - ly);
    float c01 = lx * (1.0f - ly);
    float c10 = (1.0f - lx) * ly;
    float c11 = lx * ly;

    // layer 1 accumulate directly: ff[f] consumed immediately, xy never materialized whole
    float h1[32];
#pragma unroll
    for (int j = 0; j < 32; j++) h1[j] = sb1[j];
#pragma unroll
    for (int q = 0; q < 4; q++) {
        float4 a = g00[q], b = g01[q], c = g10[q], d = g11[q];
        float ffv[4];
        ffv[0] = (a.x*c00 + b.x*c01 + c.x*c10 + d.x*c11) * szf[4*q+0];
        ffv[1] = (a.y*c00 + b.y*c01 + c.y*c10 + d.y*c11) * szf[4*q+1];
        ffv[2] = (a.z*c00 + b.z*c01 + c.z*c10 + d.z*c11) * szf[4*q+2];
        ffv[3] = (a.w*c00 + b.w*c01 + c.w*c10 + d.w*c11) * szf[4*q+3];
#pragma unroll
        for (int r = 0; r < 4; r++) {
            float ff = ffv[r];
            int f = 4*q + r;
#pragma unroll
            for (int jq = 0; jq < 8; jq++) {
                float4 w = sw1v[f * 8 + jq];
                h1[4*jq+0] = fmaf(ff, w.x, h1[4*jq+0]);
                h1[4*jq+1] = fmaf(ff, w.y, h1[4*jq+1]);
                h1[4*jq+2] = fmaf(ff, w.z, h1[4*jq+2]);
                h1[4*jq+3] = fmaf(ff, w.w, h1[4*jq+3]);
            }
        }
    }
#pragma unroll
    for (int j = 0; j < 32; j++) h1[j] = fmaxf(h1[j], 0.0f);

    float h2[32];
#pragma unroll
    for (int j = 0; j < 32; j++) h2[j] = sb2[j];
#pragma unroll
    for (int k = 0; k < 32; k++) {
        float hk = h1[k];
#pragma unroll
        for (int jq = 0; jq < 8; jq++) {
            float4 w = sw2v[k * 8 + jq];
            h2[4*jq+0] = fmaf(hk, w.x, h2[4*jq+0]);
            h2[4*jq+1] = fmaf(hk, w.y, h2[4*jq+1]);
            h2[4*jq+2] = fmaf(hk, w.z, h2[4*jq+2]);
            h2[4*jq+3] = fmaf(hk, w.w, h2[4*jq+3]);
        }
    }
    float o = sb3;
#pragma unroll
    for (int jq = 0; jq < 8; jq++) {
        float4 w = sw3v[jq];
        o = fmaf(fmaxf(h2[4*jq+0], 0.0f), w.x, o);
        o = fmaf(fmaxf(h2[4*jq+1], 0.0f), w.y, o);
        o = fmaf(fmaxf(h2[4*jq+2], 0.0f), w.z, o);
        o = fmaf(fmaxf(h2[4*jq+3], 0.0f), w.w, o);
    }
    g_fluo[zz * NPIX + p] = o;
}

// ---------------- batched 512-pt Stockham radix-8 FFT ----------------
// DIR: -1 forward, +1 inverse.
// LM: 0 complex from pick_buf(inb); 1 real from pick_real(rinsel); 2 pupil*exp(i*ab); 3 buf(inb)*buf(in2b)*invS
// SM: 0 complex to pick_buf(outb); 1 |v|^2 to pick_real(routsel); 2 v.x to pick_real(routsel)
// COL: 0 row pass (contiguous), 1 column pass (stride 512, cooperative I/O)
template <int DIR, int LM, int SM, int COL>
__global__ __launch_bounds__(256)
void fft512_kernel(int inb, int in2b, int outb, int rinsel, int routsel,
                   float* ext, const float* __restrict__ pupil,
                   const float* __restrict__ ab, float scale) {
    __shared__ float2 sA[4][SROW];
    __shared__ float2 sB[4][SROW];
    __shared__ float2 stw[512];

    int tid = threadIdx.x;
    int sub = tid >> 6, t = tid & 63;
    int sl = blockIdx.y, g4 = blockIdx.x * 4;

    for (int i = tid; i < 512; i += 256) stw[i] = g_twid[i];

    const float2* in  = pick_buf(inb);
    const float2* in2 = pick_buf(in2b);
    const float*  rin = pick_real(rinsel, nullptr);

    // ---- load ----
    if (COL == 0) {
        int row = g4 + sub;
        long base = (long)sl * NPIX + (long)row * 512;
        float sc = (LM == 3) ? g_invS : 0.0f;
#pragma unroll
        for (int r = 0; r < 8; r++) {
            int i = t + 64 * r;
            float2 v;
            if (LM == 0) v = in[base + i];
            else if (LM == 1) v = make_float2(rin[base + i], 0.0f);
            else if (LM == 2) {
                float pv = pupil[row * 512 + i];
                float sn, cs;
                sincosf(ab[base + i], &sn, &cs);
                v = make_float2(pv * cs, pv * sn);
            } else {
                float2 x = in[base + i], y = in2[base + i];
                v = make_float2((x.x*y.x - x.y*y.y) * sc, (x.x*y.y + x.y*y.x) * sc);
            }
            sA[sub][PAD(i)] = v;
        }
    } else {
        long base = (long)sl * NPIX + g4;
#pragma unroll
        for (int it = 0; it < 8; it++) {
            int row = it * 64 + (tid >> 2);
            int c = tid & 3;
            long adr = base + (long)row * 512 + c;
            float2 v;
            if (LM == 1) v = make_float2(rin[adr], 0.0f);
            else         v = in[adr];
            sA[c][PAD(row)] = v;
        }
    }
    __syncthreads();

    // ---- stage 1: ns=1 (sA -> sB) ----
    {
        float2 a[8];
#pragma unroll
        for (int r = 0; r < 8; r++) a[r] = sA[sub][PAD(t + 64 * r)];
        dft8<DIR>(a);
#pragma unroll
        for (int r = 0; r < 8; r++) sB[sub][PAD(t * 8 + r)] = a[r];
    }
    __syncthreads();

    // ---- stage 2: ns=8 (sB -> sA) ----
    {
        float2 a[8];
#pragma unroll
        for (int r = 0; r < 8; r++) a[r] = sB[sub][PAD(t + 64 * r)];
        int k = t & 7;
#pragma unroll
        for (int r = 1; r < 8; r++) {
            float2 w = stw[(k * r * 8) & 511];
            if (DIR > 0) w.y = -w.y;
            a[r] = cmulc(a[r], w);
        }
        dft8<DIR>(a);
        int bidx = (t >> 3) * 64 + k;
#pragma unroll
        for (int r = 0; r < 8; r++) sA[sub][PAD(bidx + 8 * r)] = a[r];
    }
    __syncthreads();

    // ---- stage 3: ns=64 (sA -> sB), apply scale ----
    {
        float2 a[8];
#pragma unroll
        for (int r = 0; r < 8; r++) a[r] = sA[sub][PAD(t + 64 * r)];
#pragma unroll
        for (int r = 1; r < 8; r++) {
            float2 w = stw[t * r];
            if (DIR > 0) w.y = -w.y;
            a[r] = cmulc(a[r], w);
        }
        dft8<DIR>(a);
#pragma unroll
        for (int r = 0; r < 8; r++)
            sB[sub][PAD(t + 64 * r)] = make_float2(a[r].x * scale, a[r].y * scale);
    }
    __syncthreads();

    // ---- store ----
    float2* outc = pick_buf(outb);
    float*  routp = pick_real(routsel, ext);
    if (COL == 0) {
        int row = g4 + sub;
        long base = (long)sl * NPIX + (long)row * 512;
#pragma unroll
        for (int r = 0; r < 8; r++) {
            int i = t + 64 * r;
            float2 v = sB[sub][PAD(i)];
            if (SM == 0)      outc[base + i] = v;
            else if (SM == 1) routp[base + i] = v.x*v.x + v.y*v.y;
            else              routp[base + i] = v.x;
        }
    } else {
        long base = (long)sl * NPIX + g4;
#pragma unroll
        for (int it = 0; it < 8; it++) {
            int row = it * 64 + (tid >> 2);
            int c = tid & 3;
            long adr = base + (long)row * 512 + c;
            float2 v = sB[c][PAD(row)];
            if (SM == 0)      outc[adr] = v;
            else if (SM == 1) routp[adr] = v.x*v.x + v.y*v.y;
            else              routp[adr] = v.x;
        }
    }
}

// ---------------- launch ----------------
extern "C" void kernel_launch(void* const* d_in, const int* in_sizes, int n_in,
                              void* d_out, int out_size) {
    const float* z         = (const float*)d_in[0];
    const float* grid_data = (const float*)d_in[1];
    const float* z_data    = (const float*)d_in[2];
    const float* w1        = (const float*)d_in[3];
    const float* b1        = (const float*)d_in[4];
    const float* w2        = (const float*)d_in[5];
    const float* b2        = (const float*)d_in[6];
    const float* w3        = (const float*)d_in[7];
    const float* b3        = (const float*)d_in[8];
    const float* pupil     = (const float*)d_in[9];
    const float* ab        = (const float*)d_in[10];
    const float* lerp_w    = (const float*)d_in[11];
    const int*   x0        = (const int*)d_in[12];
    const int*   y0        = (const int*)d_in[13];
    const int*   x1        = (const int*)d_in[14];
    const int*   y1        = (const int*)d_in[15];
    float* outp = (float*)d_out;

    dim3 g(128, ZM);
    const float inv = 1.0f / 512.0f;

    prep_kernel<<<1, 512>>>(z, z_data, pupil);                                  // 1
    // ifft2(P) with fused pupil*exp(i*ab) build; |.|^2 -> psf (real)
    fft512_kernel<+1, 2, 0, 0><<<g, 256>>>(0, 0, 1, 0, 0, nullptr, pupil, ab, inv);          // 2
    fft512_kernel<+1, 0, 1, 1><<<g, 256>>>(1, 0, 0, 0, 1, nullptr, nullptr, nullptr, inv);   // 3
    // render placed at launch position 4 so the ncu window captures it
    render_kernel<<<dim3(NPIX / 256, ZM), 256>>>(grid_data, w1, b1, w2, b2, w3, b3,
                                                 lerp_w, x0, y0, x1, y1);                    // 4
    // fft2(psf) -> OTF (buf0)
    fft512_kernel<-1, 1, 0, 0><<<g, 256>>>(0, 0, 1, 1, 0, nullptr, nullptr, nullptr, 1.0f);  // 5
    fft512_kernel<-1, 0, 0, 1><<<g, 256>>>(1, 0, 0, 0, 0, nullptr, nullptr, nullptr, 1.0f);  // 6
    // fft2(fluo) -> F (buf2)
    fft512_kernel<-1, 1, 0, 0><<<g, 256>>>(0, 0, 1, 0, 0, nullptr, nullptr, nullptr, 1.0f);  // 7
    fft512_kernel<-1, 0, 0, 1><<<g, 256>>>(1, 0, 2, 0, 0, nullptr, nullptr, nullptr, 1.0f);  // 8
    // ifft2(F * OTF * invS) -> real out  (cmul fused into row-pass load)
    fft512_kernel<+1, 3, 0, 0><<<g, 256>>>(2, 0, 1, 0, 0, nullptr, nullptr, nullptr, inv);   // 9
    fft512_kernel<+1, 0, 2, 1><<<g, 256>>>(1, 0, 0, 0, 2, outp, nullptr, nullptr, inv);      // 10
}

// round 8
// speedup vs baseline: 11.3339x; 1.2726x over previous
#include <cuda_runtime.h>
#include <cuda_bf16.h>
#include <math.h>

#define W 512
#define NPIX (512*512)
#define ZM 30
#define NF 16
#define TOT (ZM*NPIX)
#define SROW 580   // padded shared row (512 + 512/8 = 576 max index 574)

typedef unsigned long long ull;

// ---------------- scratch (device globals, no allocation) ----------------
__device__ float2 g_buf0[TOT];
__device__ float2 g_buf1[TOT];
__device__ float2 g_buf2[TOT];
__device__ float  g_fluo[TOT];
__device__ float  g_psf[TOT];
__device__ float  g_zfeat[ZM*NF];
__device__ float  g_invS;          // 262144 / sum(pupil)
__device__ float2 g_twid[512];     // forward twiddles exp(-2*pi*i*k/512)

__device__ __forceinline__ float2* pick_buf(int k) {
    return k == 0 ? g_buf0 : (k == 1 ? g_buf1 : g_buf2);
}
__device__ __forceinline__ float* pick_real(int k, float* ext) {
    return k == 0 ? g_fluo : (k == 1 ? g_psf : ext);
}
__device__ __forceinline__ int PAD(int i) { return i + (i >> 3); }

__device__ __forceinline__ float2 cadd(float2 a, float2 b){ return make_float2(a.x+b.x, a.y+b.y); }
__device__ __forceinline__ float2 csub(float2 a, float2 b){ return make_float2(a.x-b.x, a.y-b.y); }
__device__ __forceinline__ float2 cmulc(float2 a, float2 b){
    return make_float2(a.x*b.x - a.y*b.y, a.x*b.y + a.y*b.x);
}
template<int DIR> __device__ __forceinline__ float2 muli(float2 a){
    return (DIR > 0) ? make_float2(-a.y, a.x) : make_float2(a.y, -a.x);
}

// ---- packed fp32x2 helpers (Blackwell f32x2 pipe; 2x fp32 FMA throughput) ----
__device__ __forceinline__ ull pk2(float lo, float hi){
    ull r; asm("mov.b64 %0, {%1, %2};" : "=l"(r) : "f"(lo), "f"(hi)); return r;
}
__device__ __forceinline__ void upk2(float& lo, float& hi, ull v){
    asm("mov.b64 {%0, %1}, %2;" : "=f"(lo), "=f"(hi) : "l"(v));
}
__device__ __forceinline__ void fma2(ull& d, ull a, ull b){
    asm("fma.rn.f32x2 %0, %1, %2, %0;" : "+l"(d) : "l"(a), "l"(b));
}

// 8-point DFT in registers, b_r = sum_q a_q * exp(DIR*2*pi*i*q*r/8)
template<int DIR>
__device__ __forceinline__ void dft8(float2* a){
    const float S = 0.70710678118654752440f;
    float2 e0 = cadd(a[0], a[4]), e1 = csub(a[0], a[4]);
    float2 e2 = cadd(a[2], a[6]), e3 = csub(a[2], a[6]);
    float2 E0 = cadd(e0, e2), E2 = csub(e0, e2);
    float2 ie3 = muli<DIR>(e3);
    float2 E1 = cadd(e1, ie3), E3 = csub(e1, ie3);

    float2 o0 = cadd(a[1], a[5]), o1 = csub(a[1], a[5]);
    float2 o2 = cadd(a[3], a[7]), o3 = csub(a[3], a[7]);
    float2 O0 = cadd(o0, o2), O2 = csub(o0, o2);
    float2 io3 = muli<DIR>(o3);
    float2 O1 = cadd(o1, io3), O3 = csub(o1, io3);

    float2 W1, W3;
    if (DIR > 0) {
        W1 = make_float2(S*(O1.x - O1.y), S*(O1.x + O1.y));
        W3 = make_float2(-S*(O3.x + O3.y), S*(O3.x - O3.y));
    } else {
        W1 = make_float2(S*(O1.x + O1.y), S*(O1.y - O1.x));
        W3 = make_float2(S*(O3.y - O3.x), -S*(O3.x + O3.y));
    }
    float2 W2 = muli<DIR>(O2);

    a[0] = cadd(E0, O0); a[4] = csub(E0, O0);
    a[1] = cadd(E1, W1); a[5] = csub(E1, W1);
    a[2] = cadd(E2, W2); a[6] = csub(E2, W2);
    a[3] = cadd(E3, W3); a[7] = csub(E3, W3);
}

// ---------------- prep: twiddles, z-feature interp, pupil sum ----------------
__global__ void prep_kernel(const float* __restrict__ z,
                            const float* __restrict__ z_data,
                            const float* __restrict__ pupil) {
    int tid = threadIdx.x;   // 512 threads
    {
        float s_, c_;
        sincospif(-(float)tid * (1.0f / 256.0f), &s_, &c_);  // -2*pi*tid/512
        g_twid[tid] = make_float2(c_, s_);
    }
    if (tid < ZM) {
        float zn = 29.0f * z[tid] / 30.0f;
        float zf = floorf(zn);
        int z0 = (int)zf;
        if (z0 < 0) z0 = 0; if (z0 > ZM - 1) z0 = ZM - 1;
        int z1 = z0 + 1; if (z1 > ZM - 1) z1 = ZM - 1;
        float zl = zn - zf;
        for (int f = 0; f < NF; f++)
            g_zfeat[tid * NF + f] = z_data[z0 * NF + f] * (1.0f - zl) + z_data[z1 * NF + f] * zl;
    }
    float acc = 0.0f;
    for (int i = tid; i < NPIX; i += 512) acc += pupil[i];
    __shared__ float red[512];
    red[tid] = acc;
    __syncthreads();
    for (int s = 256; s > 0; s >>= 1) {
        if (tid < s) red[tid] += red[tid + s];
        __syncthreads();
    }
    if (tid == 0) g_invS = 262144.0f / red[0];
}

// ---------------- render: 2 pixels/thread, j-packed f32x2 MLP ----------------
__global__ __launch_bounds__(128)
void render_kernel(const float* __restrict__ grid_data,
                   const float* __restrict__ w1, const float* __restrict__ b1,
                   const float* __restrict__ w2, const float* __restrict__ b2,
                   const float* __restrict__ w3, const float* __restrict__ b3,
                   const float* __restrict__ lerp_w,
                   const int* __restrict__ x0, const int* __restrict__ y0,
                   const int* __restrict__ x1, const int* __restrict__ y1) {
    __shared__ __align__(16) float sw1[NF * 32];
    __shared__ __align__(16) float sw2[32 * 32];
    __shared__ __align__(16) float sw3[32];
    __shared__ __align__(16) float sb1[32];
    __shared__ __align__(16) float sb2[32];
    __shared__ float szf[NF];
    __shared__ float sb3;
    int tid = threadIdx.x;
    int zz = blockIdx.y;
    ((float4*)sw1)[tid] = ((const float4*)w1)[tid];                 // 512 floats
    ((float4*)sw2)[tid] = ((const float4*)w2)[tid];                 // first 512
    ((float4*)sw2)[tid + 128] = ((const float4*)w2)[tid + 128];     // second 512
    if (tid < 8)  ((float4*)sw3)[tid] = ((const float4*)w3)[tid];
    if (tid < NF) szf[tid] = g_zfeat[zz * NF + tid];
    if (tid >= 32 && tid < 64)  sb1[tid - 32] = b1[tid - 32];
    if (tid >= 64 && tid < 96)  sb2[tid - 64] = b2[tid - 64];
    if (tid == 96) sb3 = b3[0];
    __syncthreads();

    int p0 = blockIdx.x * 256 + tid;
    int p1 = p0 + 128;

    // gather coefficients for both pixels
    float lxa = lerp_w[2*p0], lya = lerp_w[2*p0+1];
    float lxb = lerp_w[2*p1], lyb = lerp_w[2*p1+1];
    const float4* a00 = (const float4*)(grid_data + (y0[p0]*W + x0[p0]) * NF);
    const float4* a01 = (const float4*)(grid_data + (y0[p0]*W + x1[p0]) * NF);
    const float4* a10 = (const float4*)(grid_data + (y1[p0]*W + x0[p0]) * NF);
    const float4* a11 = (const float4*)(grid_data + (y1[p0]*W + x1[p0]) * NF);
    const float4* b00 = (const float4*)(grid_data + (y0[p1]*W + x0[p1]) * NF);
    const float4* b01 = (const float4*)(grid_data + (y0[p1]*W + x1[p1]) * NF);
    const float4* b10 = (const float4*)(grid_data + (y1[p1]*W + x0[p1]) * NF);
    const float4* b11 = (const float4*)(grid_data + (y1[p1]*W + x1[p1]) * NF);
    float ca00 = (1.0f-lxa)*(1.0f-lya), ca01 = lxa*(1.0f-lya), ca10 = (1.0f-lxa)*lya, ca11 = lxa*lya;
    float cb00 = (1.0f-lxb)*(1.0f-lyb), cb01 = lxb*(1.0f-lyb), cb10 = (1.0f-lxb)*lyb, cb11 = lxb*lyb;

    // ---- layer 1: h1 packed over j (16 pairs per pixel) ----
    ull h1a[16], h1b[16];
    const ull* biases1 = (const ull*)sb1;
#pragma unroll
    for (int jp = 0; jp < 16; jp++) { ull bv = biases1[jp]; h1a[jp] = bv; h1b[jp] = bv; }

#pragma unroll
    for (int q = 0; q < 4; q++) {
        float4 ga0 = a00[q], ga1 = a01[q], ga2 = a10[q], ga3 = a11[q];
        float4 gb0 = b00[q], gb1 = b01[q], gb2 = b10[q], gb3 = b11[q];
        float fa[4], fb[4];
        fa[0] = (ga0.x*ca00 + ga1.x*ca01 + ga2.x*ca10 + ga3.x*ca11) * szf[4*q+0];
        fa[1] = (ga0.y*ca00 + ga1.y*ca01 + ga2.y*ca10 + ga3.y*ca11) * szf[4*q+1];
        fa[2] = (ga0.z*ca00 + ga1.z*ca01 + ga2.z*ca10 + ga3.z*ca11) * szf[4*q+2];
        fa[3] = (ga0.w*ca00 + ga1.w*ca01 + ga2.w*ca10 + ga3.w*ca11) * szf[4*q+3];
        fb[0] = (gb0.x*cb00 + gb1.x*cb01 + gb2.x*cb10 + gb3.x*cb11) * szf[4*q+0];
        fb[1] = (gb0.y*cb00 + gb1.y*cb01 + gb2.y*cb10 + gb3.y*cb11) * szf[4*q+1];
        fb[2] = (gb0.z*cb00 + gb1.z*cb01 + gb2.z*cb10 + gb3.z*cb11) * szf[4*q+2];
        fb[3] = (gb0.w*cb00 + gb1.w*cb01 + gb2.w*cb10 + gb3.w*cb11) * szf[4*q+3];
#pragma unroll
        for (int r = 0; r < 4; r++) {
            int f = 4*q + r;
            ull da = pk2(fa[r], fa[r]);
            ull db = pk2(fb[r], fb[r]);
            const ulonglong2* w1row = (const ulonglong2*)(sw1 + f * 32);
#pragma unroll
            for (int jq = 0; jq < 8; jq++) {
                ulonglong2 wp = w1row[jq];          // LDS.128: weight pairs {w[2jq..2jq+1]},{...}
                fma2(h1a[2*jq],   wp.x, da);
                fma2(h1a[2*jq+1], wp.y, da);
                fma2(h1b[2*jq],   wp.x, db);
                fma2(h1b[2*jq+1], wp.y, db);
            }
        }
    }

    // relu -> scalar h1 values (needed as per-k multipliers in layer 2)
    float s1a[32], s1b[32];
#pragma unroll
    for (int jp = 0; jp < 16; jp++) {
        float lo, hi;
        upk2(lo, hi, h1a[jp]); s1a[2*jp] = fmaxf(lo, 0.0f); s1a[2*jp+1] = fmaxf(hi, 0.0f);
        upk2(lo, hi, h1b[jp]); s1b[2*jp] = fmaxf(lo, 0.0f); s1b[2*jp+1] = fmaxf(hi, 0.0f);
    }

    // ---- layer 2: h2 packed over j ----
    ull h2a[16], h2b[16];
    const ull* biases2 = (const ull*)sb2;
#pragma unroll
    for (int jp = 0; jp < 16; jp++) { ull bv = biases2[jp]; h2a[jp] = bv; h2b[jp] = bv; }

#pragma unroll
    for (int k = 0; k < 32; k++) {
        ull ka = pk2(s1a[k], s1a[k]);
        ull kb = pk2(s1b[k], s1b[k]);
        const ulonglong2* w2row = (const ulonglong2*)(sw2 + k * 32);
#pragma unroll
        for (int jq = 0; jq < 8; jq++) {
            ulonglong2 wp = w2row[jq];
            fma2(h2a[2*jq],   wp.x, ka);
            fma2(h2a[2*jq+1], wp.y, ka);
            fma2(h2b[2*jq],   wp.x, kb);
            fma2(h2b[2*jq+1], wp.y, kb);
        }
    }

    // ---- layer 3: relu + dot ----
    float oa = sb3, ob = sb3;
#pragma unroll
    for (int jp = 0; jp < 16; jp++) {
        float lo, hi;
        upk2(lo, hi, h2a[jp]);
        oa = fmaf(fmaxf(lo, 0.0f), sw3[2*jp],   oa);
        oa = fmaf(fmaxf(hi, 0.0f), sw3[2*jp+1], oa);
        upk2(lo, hi, h2b[jp]);
        ob = fmaf(fmaxf(lo, 0.0f), sw3[2*jp],   ob);
        ob = fmaf(fmaxf(hi, 0.0f), sw3[2*jp+1], ob);
    }
    g_fluo[zz * NPIX + p0] = oa;
    g_fluo[zz * NPIX + p1] = ob;
}

// ---------------- batched 512-pt Stockham radix-8 FFT ----------------
// DIR: -1 forward, +1 inverse.
// LM: 0 complex from pick_buf(inb); 1 real from pick_real(rinsel); 2 pupil*exp(i*ab); 3 buf(inb)*buf(in2b)*invS
// SM: 0 complex to pick_buf(outb); 1 |v|^2 to pick_real(routsel); 2 v.x to pick_real(routsel)
// COL: 0 row pass (contiguous), 1 column pass (stride 512, cooperative I/O)
template <int DIR, int LM, int SM, int COL>
__global__ __launch_bounds__(256)
void fft512_kernel(int inb, int in2b, int outb, int rinsel, int routsel,
                   float* ext, const float* __restrict__ pupil,
                   const float* __restrict__ ab, float scale) {
    __shared__ float2 sA[4][SROW];
    __shared__ float2 sB[4][SROW];
    __shared__ float2 stw[512];

    int tid = threadIdx.x;
    int sub = tid >> 6, t = tid & 63;
    int sl = blockIdx.y, g4 = blockIdx.x * 4;

    for (int i = tid; i < 512; i += 256) stw[i] = g_twid[i];

    const float2* in  = pick_buf(inb);
    const float2* in2 = pick_buf(in2b);
    const float*  rin = pick_real(rinsel, nullptr);

    // ---- load ----
    if (COL == 0) {
        int row = g4 + sub;
        long base = (long)sl * NPIX + (long)row * 512;
        float sc = (LM == 3) ? g_invS : 0.0f;
#pragma unroll
        for (int r = 0; r < 8; r++) {
            int i = t + 64 * r;
            float2 v;
            if (LM == 0) v = in[base + i];
            else if (LM == 1) v = make_float2(rin[base + i], 0.0f);
            else if (LM == 2) {
                float pv = pupil[row * 512 + i];
                float sn, cs;
                sincosf(ab[base + i], &sn, &cs);
                v = make_float2(pv * cs, pv * sn);
            } else {
                float2 x = in[base + i], y = in2[base + i];
                v = make_float2((x.x*y.x - x.y*y.y) * sc, (x.x*y.y + x.y*y.x) * sc);
            }
            sA[sub][PAD(i)] = v;
        }
    } else {
        long base = (long)sl * NPIX + g4;
#pragma unroll
        for (int it = 0; it < 8; it++) {
            int row = it * 64 + (tid >> 2);
            int c = tid & 3;
            long adr = base + (long)row * 512 + c;
            float2 v;
            if (LM == 1) v = make_float2(rin[adr], 0.0f);
            else         v = in[adr];
            sA[c][PAD(row)] = v;
        }
    }
    __syncthreads();

    // ---- stage 1: ns=1 (sA -> sB) ----
    {
        float2 a[8];
#pragma unroll
        for (int r = 0; r < 8; r++) a[r] = sA[sub][PAD(t + 64 * r)];
        dft8<DIR>(a);
#pragma unroll
        for (int r = 0; r < 8; r++) sB[sub][PAD(t * 8 + r)] = a[r];
    }
    __syncthreads();

    // ---- stage 2: ns=8 (sB -> sA) ----
    {
        float2 a[8];
#pragma unroll
        for (int r = 0; r < 8; r++) a[r] = sB[sub][PAD(t + 64 * r)];
        int k = t & 7;
#pragma unroll
        for (int r = 1; r < 8; r++) {
            float2 w = stw[(k * r * 8) & 511];
            if (DIR > 0) w.y = -w.y;
            a[r] = cmulc(a[r], w);
        }
        dft8<DIR>(a);
        int bidx = (t >> 3) * 64 + k;
#pragma unroll
        for (int r = 0; r < 8; r++) sA[sub][PAD(bidx + 8 * r)] = a[r];
    }
    __syncthreads();

    // ---- stage 3: ns=64 (sA -> sB), apply scale ----
    {
        float2 a[8];
#pragma unroll
        for (int r = 0; r < 8; r++) a[r] = sA[sub][PAD(t + 64 * r)];
#pragma unroll
        for (int r = 1; r < 8; r++) {
            float2 w = stw[t * r];
            if (DIR > 0) w.y = -w.y;
            a[r] = cmulc(a[r], w);
        }
        dft8<DIR>(a);
#pragma unroll
        for (int r = 0; r < 8; r++)
            sB[sub][PAD(t + 64 * r)] = make_float2(a[r].x * scale, a[r].y * scale);
    }
    __syncthreads();

    // ---- store ----
    float2* outc = pick_buf(outb);
    float*  routp = pick_real(routsel, ext);
    if (COL == 0) {
        int row = g4 + sub;
        long base = (long)sl * NPIX + (long)row * 512;
#pragma unroll
        for (int r = 0; r < 8; r++) {
            int i = t + 64 * r;
            float2 v = sB[sub][PAD(i)];
            if (SM == 0)      outc[base + i] = v;
            else if (SM == 1) routp[base + i] = v.x*v.x + v.y*v.y;
            else              routp[base + i] = v.x;
        }
    } else {
        long base = (long)sl * NPIX + g4;
#pragma unroll
        for (int it = 0; it < 8; it++) {
            int row = it * 64 + (tid >> 2);
            int c = tid & 3;
            long adr = base + (long)row * 512 + c;
            float2 v = sB[c][PAD(row)];
            if (SM == 0)      outc[adr] = v;
            else if (SM == 1) routp[adr] = v.x*v.x + v.y*v.y;
            else              routp[adr] = v.x;
        }
    }
}

// ---------------- launch ----------------
extern "C" void kernel_launch(void* const* d_in, const int* in_sizes, int n_in,
                              void* d_out, int out_size) {
    const float* z         = (const float*)d_in[0];
    const float* grid_data = (const float*)d_in[1];
    const float* z_data    = (const float*)d_in[2];
    const float* w1        = (const float*)d_in[3];
    const float* b1        = (const float*)d_in[4];
    const float* w2        = (const float*)d_in[5];
    const float* b2        = (const float*)d_in[6];
    const float* w3        = (const float*)d_in[7];
    const float* b3        = (const float*)d_in[8];
    const float* pupil     = (const float*)d_in[9];
    const float* ab        = (const float*)d_in[10];
    const float* lerp_w    = (const float*)d_in[11];
    const int*   x0        = (const int*)d_in[12];
    const int*   y0        = (const int*)d_in[13];
    const int*   x1        = (const int*)d_in[14];
    const int*   y1        = (const int*)d_in[15];
    float* outp = (float*)d_out;

    dim3 g(128, ZM);
    const float inv = 1.0f / 512.0f;

    prep_kernel<<<1, 512>>>(z, z_data, pupil);                                  // 1
    // ifft2(P) with fused pupil*exp(i*ab) build; |.|^2 -> psf (real)
    fft512_kernel<+1, 2, 0, 0><<<g, 256>>>(0, 0, 1, 0, 0, nullptr, pupil, ab, inv);          // 2
    fft512_kernel<+1, 0, 1, 1><<<g, 256>>>(1, 0, 0, 0, 1, nullptr, nullptr, nullptr, inv);   // 3
    // render at launch position 4 so the ncu window captures it
    render_kernel<<<dim3(NPIX / 256, ZM), 128>>>(grid_data, w1, b1, w2, b2, w3, b3,
                                                 lerp_w, x0, y0, x1, y1);                    // 4
    // fft2(psf) -> OTF (buf0)
    fft512_kernel<-1, 1, 0, 0><<<g, 256>>>(0, 0, 1, 1, 0, nullptr, nullptr, nullptr, 1.0f);  // 5
    fft512_kernel<-1, 0, 0, 1><<<g, 256>>>(1, 0, 0, 0, 0, nullptr, nullptr, nullptr, 1.0f);  // 6
    // fft2(fluo) -> F (buf2)
    fft512_kernel<-1, 1, 0, 0><<<g, 256>>>(0, 0, 1, 0, 0, nullptr, nullptr, nullptr, 1.0f);  // 7
    fft512_kernel<-1, 0, 0, 1><<<g, 256>>>(1, 0, 2, 0, 0, nullptr, nullptr, nullptr, 1.0f);  // 8
    // ifft2(F * OTF * invS) -> real out  (cmul fused into row-pass load)
    fft512_kernel<+1, 3, 0, 0><<<g, 256>>>(2, 0, 1, 0, 0, nullptr, nullptr, nullptr, inv);   // 9
    fft512_kernel<+1, 0, 2, 1><<<g, 256>>>(1, 0, 0, 0, 2, outp, nullptr, nullptr, inv);      // 10
}

// round 12
// speedup vs baseline: 11.4457x; 1.0099x over previous
#include <cuda_runtime.h>
#include <cuda_bf16.h>
#include <math.h>

#define W 512
#define NPIX (512*512)
#define ZM 30
#define NF 16
#define TOT (ZM*NPIX)
#define SROW 580   // padded shared row (512 + 512/8 = 576 max index 574)

typedef unsigned long long ull;

// ---------------- scratch (device globals, no allocation) ----------------
__device__ float2 g_buf0[TOT];
__device__ float2 g_buf1[TOT];
__device__ float2 g_buf2[TOT];
__device__ float  g_fluo[TOT];
__device__ float  g_psf[TOT];
__device__ float  g_zfeat[ZM*NF];
__device__ float  g_invS;          // 262144 / sum(pupil)
__device__ float2 g_twid[512];     // forward twiddles exp(-2*pi*i*k/512)

__device__ __forceinline__ float2* pick_buf(int k) {
    return k == 0 ? g_buf0 : (k == 1 ? g_buf1 : g_buf2);
}
__device__ __forceinline__ float* pick_real(int k, float* ext) {
    return k == 0 ? g_fluo : (k == 1 ? g_psf : ext);
}
__device__ __forceinline__ int PAD(int i) { return i + (i >> 3); }

__device__ __forceinline__ float2 cadd(float2 a, float2 b){ return make_float2(a.x+b.x, a.y+b.y); }
__device__ __forceinline__ float2 csub(float2 a, float2 b){ return make_float2(a.x-b.x, a.y-b.y); }
__device__ __forceinline__ float2 cmulc(float2 a, float2 b){
    return make_float2(a.x*b.x - a.y*b.y, a.x*b.y + a.y*b.x);
}
template<int DIR> __device__ __forceinline__ float2 muli(float2 a){
    return (DIR > 0) ? make_float2(-a.y, a.x) : make_float2(a.y, -a.x);
}

// ---- packed fp32x2 helpers (Blackwell f32x2 pipe; 2x fp32 FMA throughput) ----
__device__ __forceinline__ ull pk2(float lo, float hi){
    ull r; asm("mov.b64 %0, {%1, %2};" : "=l"(r) : "f"(lo), "f"(hi)); return r;
}
__device__ __forceinline__ void upk2(float& lo, float& hi, ull v){
    asm("mov.b64 {%0, %1}, %2;" : "=f"(lo), "=f"(hi) : "l"(v));
}
__device__ __forceinline__ void fma2(ull& d, ull a, ull b){
    asm("fma.rn.f32x2 %0, %1, %2, %0;" : "+l"(d) : "l"(a), "l"(b));
}

// 8-point DFT in registers, b_r = sum_q a_q * exp(DIR*2*pi*i*q*r/8)
template<int DIR>
__device__ __forceinline__ void dft8(float2* a){
    const float S = 0.70710678118654752440f;
    float2 e0 = cadd(a[0], a[4]), e1 = csub(a[0], a[4]);
    float2 e2 = cadd(a[2], a[6]), e3 = csub(a[2], a[6]);
    float2 E0 = cadd(e0, e2), E2 = csub(e0, e2);
    float2 ie3 = muli<DIR>(e3);
    float2 E1 = cadd(e1, ie3), E3 = csub(e1, ie3);

    float2 o0 = cadd(a[1], a[5]), o1 = csub(a[1], a[5]);
    float2 o2 = cadd(a[3], a[7]), o3 = csub(a[3], a[7]);
    float2 O0 = cadd(o0, o2), O2 = csub(o0, o2);
    float2 io3 = muli<DIR>(o3);
    float2 O1 = cadd(o1, io3), O3 = csub(o1, io3);

    float2 W1, W3;
    if (DIR > 0) {
        W1 = make_float2(S*(O1.x - O1.y), S*(O1.x + O1.y));
        W3 = make_float2(-S*(O3.x + O3.y), S*(O3.x - O3.y));
    } else {
        W1 = make_float2(S*(O1.x + O1.y), S*(O1.y - O1.x));
        W3 = make_float2(S*(O3.y - O3.x), -S*(O3.x + O3.y));
    }
    float2 W2 = muli<DIR>(O2);

    a[0] = cadd(E0, O0); a[4] = csub(E0, O0);
    a[1] = cadd(E1, W1); a[5] = csub(E1, W1);
    a[2] = cadd(E2, W2); a[6] = csub(E2, W2);
    a[3] = cadd(E3, W3); a[7] = csub(E3, W3);
}

// ---------------- prep: twiddles, z-feature interp, pupil sum ----------------
__global__ void prep_kernel(const float* __restrict__ z,
                            const float* __restrict__ z_data,
                            const float* __restrict__ pupil) {
    int tid = threadIdx.x;   // 512 threads
    {
        float s_, c_;
        sincospif(-(float)tid * (1.0f / 256.0f), &s_, &c_);  // -2*pi*tid/512
        g_twid[tid] = make_float2(c_, s_);
    }
    if (tid < ZM) {
        float zn = 29.0f * z[tid] / 30.0f;
        float zf = floorf(zn);
        int z0 = (int)zf;
        if (z0 < 0) z0 = 0; if (z0 > ZM - 1) z0 = ZM - 1;
        int z1 = z0 + 1; if (z1 > ZM - 1) z1 = ZM - 1;
        float zl = zn - zf;
        for (int f = 0; f < NF; f++)
            g_zfeat[tid * NF + f] = z_data[z0 * NF + f] * (1.0f - zl) + z_data[z1 * NF + f] * zl;
    }
    float acc = 0.0f;
    for (int i = tid; i < NPIX; i += 512) acc += pupil[i];
    __shared__ float red[512];
    red[tid] = acc;
    __syncthreads();
    for (int s = 256; s > 0; s >>= 1) {
        if (tid < s) red[tid] += red[tid + s];
        __syncthreads();
    }
    if (tid == 0) g_invS = 262144.0f / red[0];
}

// ---------------- render: 2 pixels/thread, j-packed f32x2 MLP, j-split layer 2 ----------------
__global__ __launch_bounds__(128, 3)
void render_kernel(const float* __restrict__ grid_data,
                   const float* __restrict__ w1, const float* __restrict__ b1,
                   const float* __restrict__ w2, const float* __restrict__ b2,
                   const float* __restrict__ w3, const float* __restrict__ b3,
                   const float* __restrict__ lerp_w,
                   const int* __restrict__ x0, const int* __restrict__ y0,
                   const int* __restrict__ x1, const int* __restrict__ y1) {
    __shared__ __align__(16) float sw1[NF * 32];
    __shared__ __align__(16) float sw2[32 * 32];
    __shared__ __align__(16) float sw3[32];
    __shared__ __align__(16) float sb1[32];
    __shared__ __align__(16) float sb2[32];
    __shared__ float szf[NF];
    __shared__ float sb3;
    int tid = threadIdx.x;
    int zz = blockIdx.y;
    ((float4*)sw1)[tid] = ((const float4*)w1)[tid];                 // 512 floats
    ((float4*)sw2)[tid] = ((const float4*)w2)[tid];                 // first 512
    ((float4*)sw2)[tid + 128] = ((const float4*)w2)[tid + 128];     // second 512
    if (tid < 8)  ((float4*)sw3)[tid] = ((const float4*)w3)[tid];
    if (tid < NF) szf[tid] = g_zfeat[zz * NF + tid];
    if (tid >= 32 && tid < 64)  sb1[tid - 32] = b1[tid - 32];
    if (tid >= 64 && tid < 96)  sb2[tid - 64] = b2[tid - 64];
    if (tid == 96) sb3 = b3[0];
    __syncthreads();

    int p0 = blockIdx.x * 256 + tid;
    int p1 = p0 + 128;

    // gather coefficients for both pixels
    float lxa = lerp_w[2*p0], lya = lerp_w[2*p0+1];
    float lxb = lerp_w[2*p1], lyb = lerp_w[2*p1+1];
    const float4* a00 = (const float4*)(grid_data + (y0[p0]*W + x0[p0]) * NF);
    const float4* a01 = (const float4*)(grid_data + (y0[p0]*W + x1[p0]) * NF);
    const float4* a10 = (const float4*)(grid_data + (y1[p0]*W + x0[p0]) * NF);
    const float4* a11 = (const float4*)(grid_data + (y1[p0]*W + x1[p0]) * NF);
    const float4* b00 = (const float4*)(grid_data + (y0[p1]*W + x0[p1]) * NF);
    const float4* b01 = (const float4*)(grid_data + (y0[p1]*W + x1[p1]) * NF);
    const float4* b10 = (const float4*)(grid_data + (y1[p1]*W + x0[p1]) * NF);
    const float4* b11 = (const float4*)(grid_data + (y1[p1]*W + x1[p1]) * NF);
    float ca00 = (1.0f-lxa)*(1.0f-lya), ca01 = lxa*(1.0f-lya), ca10 = (1.0f-lxa)*lya, ca11 = lxa*lya;
    float cb00 = (1.0f-lxb)*(1.0f-lyb), cb01 = lxb*(1.0f-lyb), cb10 = (1.0f-lxb)*lyb, cb11 = lxb*lyb;

    // ---- layer 1: h1 packed over j (16 pairs per pixel) ----
    ull h1a[16], h1b[16];
    const ull* biases1 = (const ull*)sb1;
#pragma unroll
    for (int jp = 0; jp < 16; jp++) { ull bv = biases1[jp]; h1a[jp] = bv; h1b[jp] = bv; }

#pragma unroll
    for (int q = 0; q < 4; q++) {
        float4 ga0 = a00[q], ga1 = a01[q], ga2 = a10[q], ga3 = a11[q];
        float4 gb0 = b00[q], gb1 = b01[q], gb2 = b10[q], gb3 = b11[q];
        float fa[4], fb[4];
        fa[0] = (ga0.x*ca00 + ga1.x*ca01 + ga2.x*ca10 + ga3.x*ca11) * szf[4*q+0];
        fa[1] = (ga0.y*ca00 + ga1.y*ca01 + ga2.y*ca10 + ga3.y*ca11) * szf[4*q+1];
        fa[2] = (ga0.z*ca00 + ga1.z*ca01 + ga2.z*ca10 + ga3.z*ca11) * szf[4*q+2];
        fa[3] = (ga0.w*ca00 + ga1.w*ca01 + ga2.w*ca10 + ga3.w*ca11) * szf[4*q+3];
        fb[0] = (gb0.x*cb00 + gb1.x*cb01 + gb2.x*cb10 + gb3.x*cb11) * szf[4*q+0];
        fb[1] = (gb0.y*cb00 + gb1.y*cb01 + gb2.y*cb10 + gb3.y*cb11) * szf[4*q+1];
        fb[2] = (gb0.z*cb00 + gb1.z*cb01 + gb2.z*cb10 + gb3.z*cb11) * szf[4*q+2];
        fb[3] = (gb0.w*cb00 + gb1.w*cb01 + gb2.w*cb10 + gb3.w*cb11) * szf[4*q+3];
#pragma unroll
        for (int r = 0; r < 4; r++) {
            int f = 4*q + r;
            ull da = pk2(fa[r], fa[r]);
            ull db = pk2(fb[r], fb[r]);
            const ulonglong2* w1row = (const ulonglong2*)(sw1 + f * 32);
#pragma unroll
            for (int jq = 0; jq < 8; jq++) {
                ulonglong2 wp = w1row[jq];          // LDS.128: weight pairs
                fma2(h1a[2*jq],   wp.x, da);
                fma2(h1a[2*jq+1], wp.y, da);
                fma2(h1b[2*jq],   wp.x, db);
                fma2(h1b[2*jq+1], wp.y, db);
            }
        }
    }

    // ---- layers 2+3 fused, split over j-halves to halve h2 live registers ----
    // h1 stays packed; relu applied on the fly when forming the k multipliers.
    float oa = sb3, ob = sb3;
#pragma unroll
    for (int half = 0; half < 2; half++) {
        ull h2a[8], h2b[8];
        const ull* biases2 = (const ull*)sb2;
#pragma unroll
        for (int jp = 0; jp < 8; jp++) { ull bv = biases2[half*8 + jp]; h2a[jp] = bv; h2b[jp] = bv; }

#pragma unroll
        for (int kp = 0; kp < 16; kp++) {
            float l0, h0, l1, h1v;
            upk2(l0, h0, h1a[kp]);
            upk2(l1, h1v, h1b[kp]);
            float r0 = fmaxf(l0, 0.0f), r1 = fmaxf(h0, 0.0f);
            float s0 = fmaxf(l1, 0.0f), s1 = fmaxf(h1v, 0.0f);
            ull ka0 = pk2(r0, r0), ka1 = pk2(r1, r1);
            ull kb0 = pk2(s0, s0), kb1 = pk2(s1, s1);
            const ulonglong2* wr0 = (const ulonglong2*)(sw2 + (2*kp)   * 32 + half * 16);
            const ulonglong2* wr1 = (const ulonglong2*)(sw2 + (2*kp+1) * 32 + half * 16);
#pragma unroll
            for (int jq = 0; jq < 4; jq++) {
                ulonglong2 wp0 = wr0[jq];
                fma2(h2a[2*jq],   wp0.x, ka0);
                fma2(h2a[2*jq+1], wp0.y, ka0);
                fma2(h2b[2*jq],   wp0.x, kb0);
                fma2(h2b[2*jq+1], wp0.y, kb0);
                ulonglong2 wp1 = wr1[jq];
                fma2(h2a[2*jq],   wp1.x, ka1);
                fma2(h2a[2*jq+1], wp1.y, ka1);
                fma2(h2b[2*jq],   wp1.x, kb1);
                fma2(h2b[2*jq+1], wp1.y, kb1);
            }
        }
        // layer 3 partial dot for this half (j ascending, preserves order)
#pragma unroll
        for (int jp = 0; jp < 8; jp++) {
            float lo, hi;
            upk2(lo, hi, h2a[jp]);
            oa = fmaf(fmaxf(lo, 0.0f), sw3[half*16 + 2*jp],   oa);
            oa = fmaf(fmaxf(hi, 0.0f), sw3[half*16 + 2*jp+1], oa);
            upk2(lo, hi, h2b[jp]);
            ob = fmaf(fmaxf(lo, 0.0f), sw3[half*16 + 2*jp],   ob);
            ob = fmaf(fmaxf(hi, 0.0f), sw3[half*16 + 2*jp+1], ob);
        }
    }
    g_fluo[zz * NPIX + p0] = oa;
    g_fluo[zz * NPIX + p1] = ob;
}

// ---------------- batched 512-pt Stockham radix-8 FFT ----------------
// DIR: -1 forward, +1 inverse.
// LM: 0 complex from pick_buf(inb); 1 real from pick_real(rinsel); 2 pupil*exp(i*ab); 3 buf(inb)*buf(in2b)*invS
// SM: 0 complex to pick_buf(outb); 1 |v|^2 to pick_real(routsel); 2 v.x to pick_real(routsel)
// COL: 0 row pass (contiguous), 1 column pass (stride 512, cooperative I/O)
template <int DIR, int LM, int SM, int COL>
__global__ __launch_bounds__(256)
void fft512_kernel(int inb, int in2b, int outb, int rinsel, int routsel,
                   float* ext, const float* __restrict__ pupil,
                   const float* __restrict__ ab, float scale) {
    __shared__ float2 sA[4][SROW];
    __shared__ float2 sB[4][SROW];
    __shared__ float2 stw[512];

    int tid = threadIdx.x;
    int sub = tid >> 6, t = tid & 63;
    int sl = blockIdx.y, g4 = blockIdx.x * 4;

    for (int i = tid; i < 512; i += 256) stw[i] = g_twid[i];

    const float2* in  = pick_buf(inb);
    const float2* in2 = pick_buf(in2b);
    const float*  rin = pick_real(rinsel, nullptr);

    // ---- load ----
    if (COL == 0) {
        int row = g4 + sub;
        long base = (long)sl * NPIX + (long)row * 512;
        float sc = (LM == 3) ? g_invS : 0.0f;
#pragma unroll
        for (int r = 0; r < 8; r++) {
            int i = t + 64 * r;
            float2 v;
            if (LM == 0) v = in[base + i];
            else if (LM == 1) v = make_float2(rin[base + i], 0.0f);
            else if (LM == 2) {
                float pv = pupil[row * 512 + i];
                float sn, cs;
                sincosf(ab[base + i], &sn, &cs);
                v = make_float2(pv * cs, pv * sn);
            } else {
                float2 x = in[base + i], y = in2[base + i];
                v = make_float2((x.x*y.x - x.y*y.y) * sc, (x.x*y.y + x.y*y.x) * sc);
            }
            sA[sub][PAD(i)] = v;
        }
    } else {
        long base = (long)sl * NPIX + g4;
#pragma unroll
        for (int it = 0; it < 8; it++) {
            int row = it * 64 + (tid >> 2);
            int c = tid & 3;
            long adr = base + (long)row * 512 + c;
            float2 v;
            if (LM == 1) v = make_float2(rin[adr], 0.0f);
            else         v = in[adr];
            sA[c][PAD(row)] = v;
        }
    }
    __syncthreads();

    // ---- stage 1: ns=1 (sA -> sB) ----
    {
        float2 a[8];
#pragma unroll
        for (int r = 0; r < 8; r++) a[r] = sA[sub][PAD(t + 64 * r)];
        dft8<DIR>(a);
#pragma unroll
        for (int r = 0; r < 8; r++) sB[sub][PAD(t * 8 + r)] = a[r];
    }
    __syncthreads();

    // ---- stage 2: ns=8 (sB -> sA) ----
    {
        float2 a[8];
#pragma unroll
        for (int r = 0; r < 8; r++) a[r] = sB[sub][PAD(t + 64 * r)];
        int k = t & 7;
#pragma unroll
        for (int r = 1; r < 8; r++) {
            float2 w = stw[(k * r * 8) & 511];
            if (DIR > 0) w.y = -w.y;
            a[r] = cmulc(a[r], w);
        }
        dft8<DIR>(a);
        int bidx = (t >> 3) * 64 + k;
#pragma unroll
        for (int r = 0; r < 8; r++) sA[sub][PAD(bidx + 8 * r)] = a[r];
    }
    __syncthreads();

    // ---- stage 3: ns=64 (sA -> sB), apply scale ----
    {
        float2 a[8];
#pragma unroll
        for (int r = 0; r < 8; r++) a[r] = sA[sub][PAD(t + 64 * r)];
#pragma unroll
        for (int r = 1; r < 8; r++) {
            float2 w = stw[t * r];
            if (DIR > 0) w.y = -w.y;
            a[r] = cmulc(a[r], w);
        }
        dft8<DIR>(a);
#pragma unroll
        for (int r = 0; r < 8; r++)
            sB[sub][PAD(t + 64 * r)] = make_float2(a[r].x * scale, a[r].y * scale);
    }
    __syncthreads();

    // ---- store ----
    float2* outc = pick_buf(outb);
    float*  routp = pick_real(routsel, ext);
    if (COL == 0) {
        int row = g4 + sub;
        long base = (long)sl * NPIX + (long)row * 512;
#pragma unroll
        for (int r = 0; r < 8; r++) {
            int i = t + 64 * r;
            float2 v = sB[sub][PAD(i)];
            if (SM == 0)      outc[base + i] = v;
            else if (SM == 1) routp[base + i] = v.x*v.x + v.y*v.y;
            else              routp[base + i] = v.x;
        }
    } else {
        long base = (long)sl * NPIX + g4;
#pragma unroll
        for (int it = 0; it < 8; it++) {
            int row = it * 64 + (tid >> 2);
            int c = tid & 3;
            long adr = base + (long)row * 512 + c;
            float2 v = sB[c][PAD(row)];
            if (SM == 0)      outc[adr] = v;
            else if (SM == 1) routp[adr] = v.x*v.x + v.y*v.y;
            else              routp[adr] = v.x;
        }
    }
}

// ---------------- launch ----------------
extern "C" void kernel_launch(void* const* d_in, const int* in_sizes, int n_in,
                              void* d_out, int out_size) {
    const float* z         = (const float*)d_in[0];
    const float* grid_data = (const float*)d_in[1];
    const float* z_data    = (const float*)d_in[2];
    const float* w1        = (const float*)d_in[3];
    const float* b1        = (const float*)d_in[4];
    const float* w2        = (const float*)d_in[5];
    const float* b2        = (const float*)d_in[6];
    const float* w3        = (const float*)d_in[7];
    const float* b3        = (const float*)d_in[8];
    const float* pupil     = (const float*)d_in[9];
    const float* ab        = (const float*)d_in[10];
    const float* lerp_w    = (const float*)d_in[11];
    const int*   x0        = (const int*)d_in[12];
    const int*   y0        = (const int*)d_in[13];
    const int*   x1        = (const int*)d_in[14];
    const int*   y1        = (const int*)d_in[15];
    float* outp = (float*)d_out;

    dim3 g(128, ZM);
    const float inv = 1.0f / 512.0f;

    prep_kernel<<<1, 512>>>(z, z_data, pupil);                                  // 1
    // ifft2(P) with fused pupil*exp(i*ab) build; |.|^2 -> psf (real)
    fft512_kernel<+1, 2, 0, 0><<<g, 256>>>(0, 0, 1, 0, 0, nullptr, pupil, ab, inv);          // 2
    fft512_kernel<+1, 0, 1, 1><<<g, 256>>>(1, 0, 0, 0, 1, nullptr, nullptr, nullptr, inv);   // 3
    // render at launch position 4 so the ncu window captures it
    render_kernel<<<dim3(NPIX / 256, ZM), 128>>>(grid_data, w1, b1, w2, b2, w3, b3,
                                                 lerp_w, x0, y0, x1, y1);                    // 4
    // fft2(psf) -> OTF (buf0)
    fft512_kernel<-1, 1, 0, 0><<<g, 256>>>(0, 0, 1, 1, 0, nullptr, nullptr, nullptr, 1.0f);  // 5
    fft512_kernel<-1, 0, 0, 1><<<g, 256>>>(1, 0, 0, 0, 0, nullptr, nullptr, nullptr, 1.0f);  // 6
    // fft2(fluo) -> F (buf2)
    fft512_kernel<-1, 1, 0, 0><<<g, 256>>>(0, 0, 1, 0, 0, nullptr, nullptr, nullptr, 1.0f);  // 7
    fft512_kernel<-1, 0, 0, 1><<<g, 256>>>(1, 0, 2, 0, 0, nullptr, nullptr, nullptr, 1.0f);  // 8
    // ifft2(F * OTF * invS) -> real out  (cmul fused into row-pass load)
    fft512_kernel<+1, 3, 0, 0><<<g, 256>>>(2, 0, 1, 0, 0, nullptr, nullptr, nullptr, inv);   // 9
    fft512_kernel<+1, 0, 2, 1><<<g, 256>>>(1, 0, 0, 0, 2, outp, nullptr, nullptr, inv);      // 10
}

// round 14
// speedup vs baseline: 13.3290x; 1.1645x over previous
#include <cuda_runtime.h>
#include <cuda_bf16.h>
#include <math.h>

#define W 512
#define NPIX (512*512)
#define ZM 30
#define NF 16
#define TOT (ZM*NPIX)
#define SROW 580   // padded shared row (512 + 512/8 = 576 max index 574)

typedef unsigned long long ull;

// ---------------- scratch (device globals, no allocation) ----------------
__device__ float2 g_buf0[TOT];
__device__ float2 g_buf1[TOT];
__device__ float2 g_buf2[TOT];
__device__ float  g_fluo[TOT];
__device__ float  g_psf[TOT];
__device__ float  g_zfeat[ZM*NF];
__device__ float  g_invS;          // 262144 / sum(pupil)
__device__ float2 g_twid[512];     // forward twiddles exp(-2*pi*i*k/512)
__device__ float4 g_xyfeat[4*NPIX];   // z-independent bilinear features, [q][px] blocked

__device__ __forceinline__ float2* pick_buf(int k) {
    return k == 0 ? g_buf0 : (k == 1 ? g_buf1 : g_buf2);
}
__device__ __forceinline__ float* pick_real(int k, float* ext) {
    return k == 0 ? g_fluo : (k == 1 ? g_psf : ext);
}
__device__ __forceinline__ int PAD(int i) { return i + (i >> 3); }

__device__ __forceinline__ float2 cadd(float2 a, float2 b){ return make_float2(a.x+b.x, a.y+b.y); }
__device__ __forceinline__ float2 csub(float2 a, float2 b){ return make_float2(a.x-b.x, a.y-b.y); }
__device__ __forceinline__ float2 cmulc(float2 a, float2 b){
    return make_float2(a.x*b.x - a.y*b.y, a.x*b.y + a.y*b.x);
}
template<int DIR> __device__ __forceinline__ float2 muli(float2 a){
    return (DIR > 0) ? make_float2(-a.y, a.x) : make_float2(a.y, -a.x);
}

// ---- packed fp32x2 helpers (Blackwell f32x2 pipe; 2x fp32 FMA throughput) ----
__device__ __forceinline__ ull pk2(float lo, float hi){
    ull r; asm("mov.b64 %0, {%1, %2};" : "=l"(r) : "f"(lo), "f"(hi)); return r;
}
__device__ __forceinline__ void upk2(float& lo, float& hi, ull v){
    asm("mov.b64 {%0, %1}, %2;" : "=f"(lo), "=f"(hi) : "l"(v));
}
__device__ __forceinline__ void fma2(ull& d, ull a, ull b){
    asm("fma.rn.f32x2 %0, %1, %2, %0;" : "+l"(d) : "l"(a), "l"(b));
}

// 8-point DFT in registers, b_r = sum_q a_q * exp(DIR*2*pi*i*q*r/8)
template<int DIR>
__device__ __forceinline__ void dft8(float2* a){
    const float S = 0.70710678118654752440f;
    float2 e0 = cadd(a[0], a[4]), e1 = csub(a[0], a[4]);
    float2 e2 = cadd(a[2], a[6]), e3 = csub(a[2], a[6]);
    float2 E0 = cadd(e0, e2), E2 = csub(e0, e2);
    float2 ie3 = muli<DIR>(e3);
    float2 E1 = cadd(e1, ie3), E3 = csub(e1, ie3);

    float2 o0 = cadd(a[1], a[5]), o1 = csub(a[1], a[5]);
    float2 o2 = cadd(a[3], a[7]), o3 = csub(a[3], a[7]);
    float2 O0 = cadd(o0, o2), O2 = csub(o0, o2);
    float2 io3 = muli<DIR>(o3);
    float2 O1 = cadd(o1, io3), O3 = csub(o1, io3);

    float2 W1, W3;
    if (DIR > 0) {
        W1 = make_float2(S*(O1.x - O1.y), S*(O1.x + O1.y));
        W3 = make_float2(-S*(O3.x + O3.y), S*(O3.x - O3.y));
    } else {
        W1 = make_float2(S*(O1.x + O1.y), S*(O1.y - O1.x));
        W3 = make_float2(S*(O3.y - O3.x), -S*(O3.x + O3.y));
    }
    float2 W2 = muli<DIR>(O2);

    a[0] = cadd(E0, O0); a[4] = csub(E0, O0);
    a[1] = cadd(E1, W1); a[5] = csub(E1, W1);
    a[2] = cadd(E2, W2); a[6] = csub(E2, W2);
    a[3] = cadd(E3, W3); a[7] = csub(E3, W3);
}

// ---------------- prep: twiddles, z-feature interp, pupil sum ----------------
__global__ void prep_kernel(const float* __restrict__ z,
                            const float* __restrict__ z_data,
                            const float* __restrict__ pupil) {
    int tid = threadIdx.x;   // 512 threads
    {
        float s_, c_;
        sincospif(-(float)tid * (1.0f / 256.0f), &s_, &c_);  // -2*pi*tid/512
        g_twid[tid] = make_float2(c_, s_);
    }
    if (tid < ZM) {
        float zn = 29.0f * z[tid] / 30.0f;
        float zf = floorf(zn);
        int z0 = (int)zf;
        if (z0 < 0) z0 = 0; if (z0 > ZM - 1) z0 = ZM - 1;
        int z1 = z0 + 1; if (z1 > ZM - 1) z1 = ZM - 1;
        float zl = zn - zf;
        for (int f = 0; f < NF; f++)
            g_zfeat[tid * NF + f] = z_data[z0 * NF + f] * (1.0f - zl) + z_data[z1 * NF + f] * zl;
    }
    float acc = 0.0f;
    for (int i = tid; i < NPIX; i += 512) acc += pupil[i];
    __shared__ float red[512];
    red[tid] = acc;
    __syncthreads();
    for (int s = 256; s > 0; s >>= 1) {
        if (tid < s) red[tid] += red[tid + s];
        __syncthreads();
    }
    if (tid == 0) g_invS = 262144.0f / red[0];
}

// ---------------- feat: z-independent bilinear gather, once per pixel ----------------
__global__ __launch_bounds__(256)
void feat_kernel(const float* __restrict__ grid_data,
                 const float* __restrict__ lerp_w,
                 const int* __restrict__ x0, const int* __restrict__ y0,
                 const int* __restrict__ x1, const int* __restrict__ y1) {
    int p = blockIdx.x * 256 + threadIdx.x;
    float lx = lerp_w[2 * p], ly = lerp_w[2 * p + 1];
    const float4* g00 = (const float4*)(grid_data + (y0[p] * W + x0[p]) * NF);
    const float4* g01 = (const float4*)(grid_data + (y0[p] * W + x1[p]) * NF);
    const float4* g10 = (const float4*)(grid_data + (y1[p] * W + x0[p]) * NF);
    const float4* g11 = (const float4*)(grid_data + (y1[p] * W + x1[p]) * NF);
    float c00 = (1.0f - lx) * (1.0f - ly);
    float c01 = lx * (1.0f - ly);
    float c10 = (1.0f - lx) * ly;
    float c11 = lx * ly;
#pragma unroll
    for (int q = 0; q < 4; q++) {
        float4 a = g00[q], b = g01[q], c = g10[q], d = g11[q];
        float4 r;
        r.x = a.x*c00 + b.x*c01 + c.x*c10 + d.x*c11;
        r.y = a.y*c00 + b.y*c01 + c.y*c10 + d.y*c11;
        r.z = a.z*c00 + b.z*c01 + c.z*c10 + d.z*c11;
        r.w = a.w*c00 + b.w*c01 + c.w*c10 + d.w*c11;
        g_xyfeat[q * NPIX + p] = r;   // blocked [q][px]: warp reads are contiguous
    }
}

// ---------------- render: 2 pixels/thread, j-packed f32x2 MLP, coalesced features ----------------
__global__ __launch_bounds__(128, 3)
void render_kernel(const float* __restrict__ w1, const float* __restrict__ b1,
                   const float* __restrict__ w2, const float* __restrict__ b2,
                   const float* __restrict__ w3, const float* __restrict__ b3) {
    __shared__ __align__(16) float sw1[NF * 32];
    __shared__ __align__(16) float sw2[32 * 32];
    __shared__ __align__(16) float sw3[32];
    __shared__ __align__(16) float sb1[32];
    __shared__ __align__(16) float sb2[32];
    __shared__ float szf[NF];
    __shared__ float sb3;
    int tid = threadIdx.x;
    int zz = blockIdx.y;
    ((float4*)sw1)[tid] = ((const float4*)w1)[tid];                 // 512 floats
    ((float4*)sw2)[tid] = ((const float4*)w2)[tid];                 // first 512
    ((float4*)sw2)[tid + 128] = ((const float4*)w2)[tid + 128];     // second 512
    if (tid < 8)  ((float4*)sw3)[tid] = ((const float4*)w3)[tid];
    if (tid < NF) szf[tid] = g_zfeat[zz * NF + tid];
    if (tid >= 32 && tid < 64)  sb1[tid - 32] = b1[tid - 32];
    if (tid >= 64 && tid < 96)  sb2[tid - 64] = b2[tid - 64];
    if (tid == 96) sb3 = b3[0];
    __syncthreads();

    int p0 = blockIdx.x * 256 + tid;
    int p1 = p0 + 128;

    // ---- layer 1: h1 packed over j (16 pairs per pixel) ----
    ull h1a[16], h1b[16];
    const ull* biases1 = (const ull*)sb1;
#pragma unroll
    for (int jp = 0; jp < 16; jp++) { ull bv = biases1[jp]; h1a[jp] = bv; h1b[jp] = bv; }

#pragma unroll
    for (int q = 0; q < 4; q++) {
        float4 xa = g_xyfeat[q * NPIX + p0];   // coalesced: lane-consecutive 16B
        float4 xb = g_xyfeat[q * NPIX + p1];
        float fa[4], fb[4];
        fa[0] = xa.x * szf[4*q+0];
        fa[1] = xa.y * szf[4*q+1];
        fa[2] = xa.z * szf[4*q+2];
        fa[3] = xa.w * szf[4*q+3];
        fb[0] = xb.x * szf[4*q+0];
        fb[1] = xb.y * szf[4*q+1];
        fb[2] = xb.z * szf[4*q+2];
        fb[3] = xb.w * szf[4*q+3];
#pragma unroll
        for (int r = 0; r < 4; r++) {
            int f = 4*q + r;
            ull da = pk2(fa[r], fa[r]);
            ull db = pk2(fb[r], fb[r]);
            const ulonglong2* w1row = (const ulonglong2*)(sw1 + f * 32);
#pragma unroll
            for (int jq = 0; jq < 8; jq++) {
                ulonglong2 wp = w1row[jq];          // LDS.128: weight pairs
                fma2(h1a[2*jq],   wp.x, da);
                fma2(h1a[2*jq+1], wp.y, da);
                fma2(h1b[2*jq],   wp.x, db);
                fma2(h1b[2*jq+1], wp.y, db);
            }
        }
    }

    // ---- layers 2+3 fused, split over j-halves to halve h2 live registers ----
    float oa = sb3, ob = sb3;
#pragma unroll
    for (int half = 0; half < 2; half++) {
        ull h2a[8], h2b[8];
        const ull* biases2 = (const ull*)sb2;
#pragma unroll
        for (int jp = 0; jp < 8; jp++) { ull bv = biases2[half*8 + jp]; h2a[jp] = bv; h2b[jp] = bv; }

#pragma unroll
        for (int kp = 0; kp < 16; kp++) {
            float l0, h0, l1, h1v;
            upk2(l0, h0, h1a[kp]);
            upk2(l1, h1v, h1b[kp]);
            float r0 = fmaxf(l0, 0.0f), r1 = fmaxf(h0, 0.0f);
            float s0 = fmaxf(l1, 0.0f), s1 = fmaxf(h1v, 0.0f);
            ull ka0 = pk2(r0, r0), ka1 = pk2(r1, r1);
            ull kb0 = pk2(s0, s0), kb1 = pk2(s1, s1);
            const ulonglong2* wr0 = (const ulonglong2*)(sw2 + (2*kp)   * 32 + half * 16);
            const ulonglong2* wr1 = (const ulonglong2*)(sw2 + (2*kp+1) * 32 + half * 16);
#pragma unroll
            for (int jq = 0; jq < 4; jq++) {
                ulonglong2 wp0 = wr0[jq];
                fma2(h2a[2*jq],   wp0.x, ka0);
                fma2(h2a[2*jq+1], wp0.y, ka0);
                fma2(h2b[2*jq],   wp0.x, kb0);
                fma2(h2b[2*jq+1], wp0.y, kb0);
                ulonglong2 wp1 = wr1[jq];
                fma2(h2a[2*jq],   wp1.x, ka1);
                fma2(h2a[2*jq+1], wp1.y, ka1);
                fma2(h2b[2*jq],   wp1.x, kb1);
                fma2(h2b[2*jq+1], wp1.y, kb1);
            }
        }
        // layer 3 partial dot for this half (j ascending, preserves order)
#pragma unroll
        for (int jp = 0; jp < 8; jp++) {
            float lo, hi;
            upk2(lo, hi, h2a[jp]);
            oa = fmaf(fmaxf(lo, 0.0f), sw3[half*16 + 2*jp],   oa);
            oa = fmaf(fmaxf(hi, 0.0f), sw3[half*16 + 2*jp+1], oa);
            upk2(lo, hi, h2b[jp]);
            ob = fmaf(fmaxf(lo, 0.0f), sw3[half*16 + 2*jp],   ob);
            ob = fmaf(fmaxf(hi, 0.0f), sw3[half*16 + 2*jp+1], ob);
        }
    }
    g_fluo[zz * NPIX + p0] = oa;
    g_fluo[zz * NPIX + p1] = ob;
}

// ---------------- batched 512-pt Stockham radix-8 FFT ----------------
// DIR: -1 forward, +1 inverse.
// LM: 0 complex from pick_buf(inb); 1 real from pick_real(rinsel); 2 pupil*exp(i*ab); 3 buf(inb)*buf(in2b)*invS
// SM: 0 complex to pick_buf(outb); 1 |v|^2 to pick_real(routsel); 2 v.x to pick_real(routsel)
// COL: 0 row pass (contiguous), 1 column pass (stride 512, cooperative I/O)
template <int DIR, int LM, int SM, int COL>
__global__ __launch_bounds__(256)
void fft512_kernel(int inb, int in2b, int outb, int rinsel, int routsel,
                   float* ext, const float* __restrict__ pupil,
                   const float* __restrict__ ab, float scale) {
    __shared__ float2 sA[4][SROW];
    __shared__ float2 sB[4][SROW];
    __shared__ float2 stw[512];

    int tid = threadIdx.x;
    int sub = tid >> 6, t = tid & 63;
    int sl = blockIdx.y, g4 = blockIdx.x * 4;

    for (int i = tid; i < 512; i += 256) stw[i] = g_twid[i];

    const float2* in  = pick_buf(inb);
    const float2* in2 = pick_buf(in2b);
    const float*  rin = pick_real(rinsel, nullptr);

    // ---- load ----
    if (COL == 0) {
        int row = g4 + sub;
        long base = (long)sl * NPIX + (long)row * 512;
        float sc = (LM == 3) ? g_invS : 0.0f;
#pragma unroll
        for (int r = 0; r < 8; r++) {
            int i = t + 64 * r;
            float2 v;
            if (LM == 0) v = in[base + i];
            else if (LM == 1) v = make_float2(rin[base + i], 0.0f);
            else if (LM == 2) {
                float pv = pupil[row * 512 + i];
                float sn, cs;
                sincosf(ab[base + i], &sn, &cs);
                v = make_float2(pv * cs, pv * sn);
            } else {
                float2 x = in[base + i], y = in2[base + i];
                v = make_float2((x.x*y.x - x.y*y.y) * sc, (x.x*y.y + x.y*y.x) * sc);
            }
            sA[sub][PAD(i)] = v;
        }
    } else {
        long base = (long)sl * NPIX + g4;
#pragma unroll
        for (int it = 0; it < 8; it++) {
            int row = it * 64 + (tid >> 2);
            int c = tid & 3;
            long adr = base + (long)row * 512 + c;
            float2 v;
            if (LM == 1) v = make_float2(rin[adr], 0.0f);
            else         v = in[adr];
            sA[c][PAD(row)] = v;
        }
    }
    __syncthreads();

    // ---- stage 1: ns=1 (sA -> sB) ----
    {
        float2 a[8];
#pragma unroll
        for (int r = 0; r < 8; r++) a[r] = sA[sub][PAD(t + 64 * r)];
        dft8<DIR>(a);
#pragma unroll
        for (int r = 0; r < 8; r++) sB[sub][PAD(t * 8 + r)] = a[r];
    }
    __syncthreads();

    // ---- stage 2: ns=8 (sB -> sA) ----
    {
        float2 a[8];
#pragma unroll
        for (int r = 0; r < 8; r++) a[r] = sB[sub][PAD(t + 64 * r)];
        int k = t & 7;
#pragma unroll
        for (int r = 1; r < 8; r++) {
            float2 w = stw[(k * r * 8) & 511];
            if (DIR > 0) w.y = -w.y;
            a[r] = cmulc(a[r], w);
        }
        dft8<DIR>(a);
        int bidx = (t >> 3) * 64 + k;
#pragma unroll
        for (int r = 0; r < 8; r++) sA[sub][PAD(bidx + 8 * r)] = a[r];
    }
    __syncthreads();

    // ---- stage 3: ns=64 (sA -> sB), apply scale ----
    {
        float2 a[8];
#pragma unroll
        for (int r = 0; r < 8; r++) a[r] = sA[sub][PAD(t + 64 * r)];
#pragma unroll
        for (int r = 1; r < 8; r++) {
            float2 w = stw[t * r];
            if (DIR > 0) w.y = -w.y;
            a[r] = cmulc(a[r], w);
        }
        dft8<DIR>(a);
#pragma unroll
        for (int r = 0; r < 8; r++)
            sB[sub][PAD(t + 64 * r)] = make_float2(a[r].x * scale, a[r].y * scale);
    }
    __syncthreads();

    // ---- store ----
    float2* outc = pick_buf(outb);
    float*  routp = pick_real(routsel, ext);
    if (COL == 0) {
        int row = g4 + sub;
        long base = (long)sl * NPIX + (long)row * 512;
#pragma unroll
        for (int r = 0; r < 8; r++) {
            int i = t + 64 * r;
            float2 v = sB[sub][PAD(i)];
            if (SM == 0)      outc[base + i] = v;
            else if (SM == 1) routp[base + i] = v.x*v.x + v.y*v.y;
            else              routp[base + i] = v.x;
        }
    } else {
        long base = (long)sl * NPIX + g4;
#pragma unroll
        for (int it = 0; it < 8; it++) {
            int row = it * 64 + (tid >> 2);
            int c = tid & 3;
            long adr = base + (long)row * 512 + c;
            float2 v = sB[c][PAD(row)];
            if (SM == 0)      outc[adr] = v;
            else if (SM == 1) routp[adr] = v.x*v.x + v.y*v.y;
            else              routp[adr] = v.x;
        }
    }
}

// ---------------- launch ----------------
extern "C" void kernel_launch(void* const* d_in, const int* in_sizes, int n_in,
                              void* d_out, int out_size) {
    const float* z         = (const float*)d_in[0];
    const float* grid_data = (const float*)d_in[1];
    const float* z_data    = (const float*)d_in[2];
    const float* w1        = (const float*)d_in[3];
    const float* b1        = (const float*)d_in[4];
    const float* w2        = (const float*)d_in[5];
    const float* b2        = (const float*)d_in[6];
    const float* w3        = (const float*)d_in[7];
    const float* b3        = (const float*)d_in[8];
    const float* pupil     = (const float*)d_in[9];
    const float* ab        = (const float*)d_in[10];
    const float* lerp_w    = (const float*)d_in[11];
    const int*   x0        = (const int*)d_in[12];
    const int*   y0        = (const int*)d_in[13];
    const int*   x1        = (const int*)d_in[14];
    const int*   y1        = (const int*)d_in[15];
    float* outp = (float*)d_out;

    dim3 g(128, ZM);
    const float inv = 1.0f / 512.0f;

    prep_kernel<<<1, 512>>>(z, z_data, pupil);                                  // 1
    feat_kernel<<<NPIX / 256, 256>>>(grid_data, lerp_w, x0, y0, x1, y1);        // 2
    // ifft2(P) with fused pupil*exp(i*ab) build
    fft512_kernel<+1, 2, 0, 0><<<g, 256>>>(0, 0, 1, 0, 0, nullptr, pupil, ab, inv);          // 3
    // render at launch position 4 so the ncu window captures it
    render_kernel<<<dim3(NPIX / 256, ZM), 128>>>(w1, b1, w2, b2, w3, b3);                    // 4
    fft512_kernel<+1, 0, 1, 1><<<g, 256>>>(1, 0, 0, 0, 1, nullptr, nullptr, nullptr, inv);   // 5
    // fft2(psf) -> OTF (buf0)
    fft512_kernel<-1, 1, 0, 0><<<g, 256>>>(0, 0, 1, 1, 0, nullptr, nullptr, nullptr, 1.0f);  // 6
    fft512_kernel<-1, 0, 0, 1><<<g, 256>>>(1, 0, 0, 0, 0, nullptr, nullptr, nullptr, 1.0f);  // 7
    // fft2(fluo) -> F (buf2)
    fft512_kernel<-1, 1, 0, 0><<<g, 256>>>(0, 0, 1, 0, 0, nullptr, nullptr, nullptr, 1.0f);  // 8
    fft512_kernel<-1, 0, 0, 1><<<g, 256>>>(1, 0, 2, 0, 0, nullptr, nullptr, nullptr, 1.0f);  // 9
    // ifft2(F * OTF * invS) -> real out  (cmul fused into row-pass load)
    fft512_kernel<+1, 3, 0, 0><<<g, 256>>>(2, 0, 1, 0, 0, nullptr, nullptr, nullptr, inv);   // 10
    fft512_kernel<+1, 0, 2, 1><<<g, 256>>>(1, 0, 0, 0, 2, outp, nullptr, nullptr, inv);      // 11
}